// round 12
// baseline (speedup 1.0000x reference)
#include <cuda_runtime.h>
#include <cuda_fp16.h>
#include <cstdint>

#define BBATCH 2
#define SEQ    2048
#define DMODEL 1024
#define NHEAD  16
#define DHEAD  64
#define MROWS  (BBATCH*SEQ)     // 4096

// ---------------------------------------------------------------------------
// Scratch (device globals; no allocation allowed)
// ---------------------------------------------------------------------------
__device__ __half g_wh[4*DMODEL*DMODEL];   // W^T [n][k] fp16 (q,k,v,o)
__device__ __half g_xh[MROWS*DMODEL];      // x fp16
__device__ __half g_qh[MROWS*DMODEL];
__device__ __half g_kh[MROWS*DMODEL];
__device__ __half g_vh[MROWS*DMODEL];
__device__ __half g_ch[MROWS*DMODEL];      // ctx fp16
__device__ int    g_ctr;                   // persistent-flash work counter

// ---------------------------------------------------------------------------
// PTX helpers (sm_80-baseline; valid on plain sm_103 target)
// ---------------------------------------------------------------------------
__device__ __forceinline__ uint32_t smem_u32(const void* p) {
    uint32_t a;
    asm("{ .reg .u64 t; cvta.to.shared.u64 t, %1; cvt.u32.u64 %0, t; }" : "=r"(a) : "l"(p));
    return a;
}
__device__ __forceinline__ void cp16(uint32_t s, const void* g) {
    asm volatile("cp.async.cg.shared.global [%0], [%1], 16;" :: "r"(s), "l"(g));
}
__device__ __forceinline__ void cp_commit() {
    asm volatile("cp.async.commit_group;" ::: "memory");
}
template<int N> __device__ __forceinline__ void cp_wait() {
    asm volatile("cp.async.wait_group %0;" :: "n"(N) : "memory");
}
__device__ __forceinline__ void ldsm4(uint32_t* r, uint32_t a) {
    asm volatile("ldmatrix.sync.aligned.m8n8.x4.shared.b16 {%0,%1,%2,%3}, [%4];"
        : "=r"(r[0]), "=r"(r[1]), "=r"(r[2]), "=r"(r[3]) : "r"(a));
}
__device__ __forceinline__ void ldsm4t(uint32_t* r, uint32_t a) {
    asm volatile("ldmatrix.sync.aligned.m8n8.x4.trans.shared.b16 {%0,%1,%2,%3}, [%4];"
        : "=r"(r[0]), "=r"(r[1]), "=r"(r[2]), "=r"(r[3]) : "r"(a));
}
__device__ __forceinline__ void mma16816(float* c, const uint32_t* a,
                                         uint32_t b0, uint32_t b1) {
    asm volatile("mma.sync.aligned.m16n8k16.row.col.f32.f16.f16.f32 "
        "{%0,%1,%2,%3}, {%4,%5,%6,%7}, {%8,%9}, {%0,%1,%2,%3};"
        : "+f"(c[0]), "+f"(c[1]), "+f"(c[2]), "+f"(c[3])
        : "r"(a[0]), "r"(a[1]), "r"(a[2]), "r"(a[3]), "r"(b0), "r"(b1));
}
__device__ __forceinline__ uint32_t pack_h2(float a, float b) {
    __half2 h = __floats2half2_rn(a, b);
    return *reinterpret_cast<uint32_t*>(&h);
}

// FFMA-only exp2 (deg-4 poly, ~4e-5 rel err)
__device__ __forceinline__ float fexp2(float t) {
    float z = t + 12582912.0f;                 // 1.5*2^23 magic round
    int   i = __float_as_int(z) << 23;
    float f = t - (z - 12582912.0f);           // f in [-0.5, 0.5]
    float p = 0.0096181291f;
    p = fmaf(p, f, 0.0555041087f);
    p = fmaf(p, f, 0.2402265069f);
    p = fmaf(p, f, 0.6931471806f);
    p = fmaf(p, f, 1.0f);
    return __int_as_float(__float_as_int(p) + i);
}

#define K1F 0.18033688011112042f   // log2(e)/sqrt(64)

// ---------------------------------------------------------------------------
// Conversions
// ---------------------------------------------------------------------------
__global__ __launch_bounds__(256)
void xconv_kernel(const float* __restrict__ in)
{
    int i = (blockIdx.x * 256 + threadIdx.x) * 4;
    float4 v = *(const float4*)(in + i);
    uint2 u = make_uint2(pack_h2(v.x, v.y), pack_h2(v.z, v.w));
    *(uint2*)(g_xh + i) = u;
}

// Transpose W[k][n] fp32 -> W^T[n][k] fp16
__global__ __launch_bounds__(256)
void wconv_kernel(const float* __restrict__ Wq, const float* __restrict__ Wk,
                  const float* __restrict__ Wv, const float* __restrict__ Wo)
{
    __shared__ float ts[32][33];
    int z = blockIdx.z;
    const float* W = (z == 0) ? Wq : (z == 1) ? Wk : (z == 2) ? Wv : Wo;
    int n0 = blockIdx.x * 32, k0 = blockIdx.y * 32;
    int tx = threadIdx.x, ty = threadIdx.y;   // 32 x 8
#pragma unroll
    for (int j = 0; j < 4; j++)
        ts[ty + 8 * j][tx] = W[(size_t)(k0 + ty + 8 * j) * DMODEL + n0 + tx];
    __syncthreads();
    size_t wb = (size_t)z * DMODEL * DMODEL;
#pragma unroll
    for (int j = 0; j < 4; j++) {
        float v = ts[tx][ty + 8 * j];
        g_wh[wb + (size_t)(n0 + ty + 8 * j) * DMODEL + k0 + tx] = __float2half_rn(v);
    }
}

__global__ void reset_ctr_kernel() { g_ctr = 0; }

// swizzled half-offset within a row-major [rows][64] tile
__device__ __forceinline__ uint32_t gswz(int row, int seg) {
    return (uint32_t)(row * 64 + ((seg ^ (row & 7)) << 3));
}

// ---------------------------------------------------------------------------
// fp16 HMMA GEMM: C = A @ W^T (+bias).  CTA 256x128, 8 warps (4m x 2n ->
// 64x64 warp tiles), K-slab 64, 3-stage cp.async (prefetch-before-compute,
// one sync per slab), XOR-swizzled smem (48KB/stage, 144KB -> 1 CTA/SM).
// ---------------------------------------------------------------------------
#define G2A_ELE (256*64)                    // 16384 halves
#define G2B_ELE (128*64)                    // 8192 halves
#define G2STAGE_ELE (G2A_ELE + G2B_ELE)     // 24576 halves
#define GEMM_SMEM_BYTES (3*G2STAGE_ELE*2)   // 147456

template<int MODE>   // 0: fp16 out, 1: fp32 out + bias
__device__ __forceinline__ void gemm_device(const __half* __restrict__ A,
                                            const __half* __restrict__ B,
                                            int m0, int n0,
                                            __half* __restrict__ hout,
                                            float* __restrict__ fout,
                                            const float* __restrict__ bias)
{
    extern __shared__ __half gsm[];
    const int tid = threadIdx.x;
    const int wid = tid >> 5, lane = tid & 31;
    const int wm = (wid >> 1) * 64, wn = (wid & 1) * 64;
    const uint32_t sbase = smem_u32(gsm);

    // per k-slab: A 256 rows + B 128 rows, 8 segs each = 3072 chunks
    auto prefetch = [&](int s, int k0) {
#pragma unroll
        for (int t = 0; t < 12; t++) {
            int c = tid + t * 256;          // 0..3071
            const __half* g;
            uint32_t abase;
            int row, seg;
            if (t < 8) {                    // A: c in 0..2047
                row = c >> 3; seg = c & 7;
                g = A + (size_t)(m0 + row) * DMODEL + k0 + seg * 8;
                abase = 0;
            } else {                        // B: c in 2048..3071
                int rc = c - 2048;
                row = rc >> 3; seg = rc & 7;
                g = B + (size_t)(n0 + row) * DMODEL + k0 + seg * 8;
                abase = G2A_ELE;
            }
            cp16(sbase + (uint32_t)(s * G2STAGE_ELE + abase) * 2 + gswz(row, seg) * 2, g);
        }
    };
    prefetch(0, 0);  cp_commit();
    prefetch(1, 64); cp_commit();

    float acc[4][8][4];
#pragma unroll
    for (int i = 0; i < 4; i++)
#pragma unroll
        for (int j = 0; j < 8; j++)
#pragma unroll
            for (int e = 0; e < 4; e++) acc[i][j][e] = 0.f;

    const int NC = DMODEL / 64;   // 16 slab iterations
    for (int c = 0; c < NC; c++) {
        cp_wait<1>();
        __syncthreads();           // all warps done with stage (c-1)%3; stage c%3 loaded

        // prefetch into stage (c+2)%3 == (c-1)%3 (freed by the barrier above)
        if (c + 2 < NC) prefetch((c + 2) % 3, (c + 2) * 64);
        cp_commit();

        const int s = c % 3;
        const uint32_t st = sbase + (uint32_t)(s * G2STAGE_ELE) * 2;

#pragma unroll
        for (int ks = 0; ks < 4; ks++) {
            uint32_t af[4][4];
#pragma unroll
            for (int mf = 0; mf < 4; mf++)
                ldsm4(af[mf], st + gswz(wm + mf * 16 + (lane & 15),
                                        2 * ks + (lane >> 4)) * 2);
#pragma unroll
            for (int p = 0; p < 4; p++) {
                uint32_t b4[4];
                ldsm4(b4, st + (uint32_t)(G2A_ELE * 2)
                          + gswz(wn + p * 16 + (lane & 15), 2 * ks + (lane >> 4)) * 2);
#pragma unroll
                for (int mf = 0; mf < 4; mf++) {
                    mma16816(acc[mf][2 * p],     af[mf], b4[0], b4[2]);
                    mma16816(acc[mf][2 * p + 1], af[mf], b4[1], b4[3]);
                }
            }
        }
    }

    const int r0 = lane >> 2, cc = (lane & 3) * 2;
#pragma unroll
    for (int mf = 0; mf < 4; mf++) {
        int m = m0 + wm + mf * 16 + r0;
#pragma unroll
        for (int nf = 0; nf < 8; nf++) {
            int n = n0 + wn + (nf >> 1) * 16 + (nf & 1) * 8 + cc;
            if (MODE == 0) {
                *(uint32_t*)(hout + (size_t)m * DMODEL + n) =
                    pack_h2(acc[mf][nf][0], acc[mf][nf][1]);
                *(uint32_t*)(hout + (size_t)(m + 8) * DMODEL + n) =
                    pack_h2(acc[mf][nf][2], acc[mf][nf][3]);
            } else {
                float b0 = bias[n], b1 = bias[n + 1];
                *(float2*)(fout + (size_t)m * DMODEL + n) =
                    make_float2(acc[mf][nf][0] + b0, acc[mf][nf][1] + b1);
                *(float2*)(fout + (size_t)(m + 8) * DMODEL + n) =
                    make_float2(acc[mf][nf][2] + b0, acc[mf][nf][3] + b1);
            }
        }
    }
}

__global__ __launch_bounds__(256, 1)
void qkv_gemm_kernel()
{
    const int z = blockIdx.z;
    __half* out = (z == 0) ? g_qh : (z == 1) ? g_kh : g_vh;
    gemm_device<0>(g_xh, g_wh + (size_t)z * DMODEL * DMODEL,
                   blockIdx.y * 256, blockIdx.x * 128, out, nullptr, nullptr);
}

__global__ __launch_bounds__(256, 1)
void out_gemm_kernel(const float* __restrict__ bo, float* __restrict__ out)
{
    gemm_device<1>(g_ch, g_wh + (size_t)3 * DMODEL * DMODEL,
                   blockIdx.y * 256, blockIdx.x * 128, nullptr, out, bo);
}

// ---------------------------------------------------------------------------
// Flash attention: fp16 HMMA, causal, no-max softmax, FFMA exp2.
// PERSISTENT: grid = 3*148 CTAs; work units (qi,h,b) sorted big-first popped
// from a global atomic counter (LPT schedule, no wave quantization).
// Per unit: 128 q-rows (8 warps x m16), KV tiles of 64, 3-stage cp.async,
// one sync per tile, stride-72 padded smem, masked/unmasked paths.
// ---------------------------------------------------------------------------
#define FSTRIDE 72
#define FQ_ELE (128*FSTRIDE)        // 9216 halves
#define FKV_ELE (64*FSTRIDE)        // 4608 halves
#define FSTAGE_ELE (2*FKV_ELE)      // K + V
#define FLASH_SMEM_BYTES ((FQ_ELE + 3*FSTAGE_ELE)*2)   // 73728
#define FLASH_GRID (3*148)
#define N_UNITS (16*NHEAD*BBATCH)   // 512

template<bool MASKED>
__device__ __forceinline__ void flash_half(
    int c32, int lr32, int rowlo, int r0g, int cq, int lane,
    uint32_t kbase, uint32_t vbase,
    const uint32_t (&qa)[4][4],
    float (&oacc)[8][4], float& l0, float& l1)
{
    uint32_t pa[2][4];
    bool act2[2];

    // S = Q K^T for 2 jp sub-tiles (16 kv cols each), exp -> P
#pragma unroll
    for (int jp2 = 0; jp2 < 2; jp2++) {
        const int c16 = c32 + 16 * jp2;
        act2[jp2] = !MASKED || (c16 <= rowlo + 15);
        if (MASKED && !act2[jp2]) continue;
        float sc[2][4] = {};
        uint32_t kb[4];
        const int jrow = lr32 + 16 * jp2 + (lane & 15);
#pragma unroll
        for (int ks = 0; ks < 4; ks++) {
            ldsm4(kb, kbase + (uint32_t)(jrow * FSTRIDE + ks * 16 + (lane >> 4) * 8) * 2);
            mma16816(sc[0], qa[ks], kb[0], kb[2]);
            mma16816(sc[1], qa[ks], kb[1], kb[3]);
        }
#pragma unroll
        for (int jj = 0; jj < 2; jj++) {
            float p0, p1, p2, p3;
            if (MASKED) {
                const int cg = c16 + 8 * jj + cq;
                p0 = (cg     <= r0g    ) ? fexp2(sc[jj][0] * K1F) : 0.f;
                p1 = (cg + 1 <= r0g    ) ? fexp2(sc[jj][1] * K1F) : 0.f;
                p2 = (cg     <= r0g + 8) ? fexp2(sc[jj][2] * K1F) : 0.f;
                p3 = (cg + 1 <= r0g + 8) ? fexp2(sc[jj][3] * K1F) : 0.f;
            } else {
                p0 = fexp2(sc[jj][0] * K1F);
                p1 = fexp2(sc[jj][1] * K1F);
                p2 = fexp2(sc[jj][2] * K1F);
                p3 = fexp2(sc[jj][3] * K1F);
            }
            l0 += p0 + p1;
            l1 += p2 + p3;
            pa[jp2][2 * jj]     = pack_h2(p0, p1);
            pa[jp2][2 * jj + 1] = pack_h2(p2, p3);
        }
    }

    // O += P V (partial over this half's 32 kv rows)
#pragma unroll
    for (int jpd = 0; jpd < 4; jpd++) {
        uint32_t vb[4];
#pragma unroll
        for (int jp2 = 0; jp2 < 2; jp2++) {
            if (MASKED && !act2[jp2]) continue;
            const int vrow = lr32 + 16 * jp2 + (lane & 15);
            ldsm4t(vb, vbase + (uint32_t)(vrow * FSTRIDE + 16 * jpd + (lane >> 4) * 8) * 2);
            mma16816(oacc[2 * jpd],     pa[jp2], vb[0], vb[1]);
            mma16816(oacc[2 * jpd + 1], pa[jp2], vb[2], vb[3]);
        }
    }
}

__global__ __launch_bounds__(256, 3)
void flash_kernel()
{
    extern __shared__ __half fsm[];
    __shared__ int s_w;
    const int tid = threadIdx.x, wid = tid >> 5, lane = tid & 31;
    const uint32_t sbase = smem_u32(fsm);

    for (;;) {
        if (tid == 0) s_w = atomicAdd(&g_ctr, 1);
        __syncthreads();               // publishes s_w; also fences smem reuse
        const int w = s_w;
        if (w >= N_UNITS) return;

        // big-first (LPT): qi descends as w grows through groups of 32
        const int qi = 15 - (w >> 5);
        const int h  = w & 15;
        const int b  = (w >> 4) & 1;
        const int q0 = qi * 128;
        const int n_tiles = 2 * qi + 2;
        const size_t gb = (size_t)b * SEQ * DMODEL + (size_t)h * DHEAD;

        // Q tile: 128 x 64 halves
#pragma unroll
        for (int t = 0; t < 4; t++) {
            int c = tid + t * 256;
            int row = c >> 3, seg = c & 7;
            cp16(sbase + (uint32_t)(row * FSTRIDE + seg * 8) * 2,
                 g_qh + gb + (size_t)(q0 + row) * DMODEL + seg * 8);
        }
        cp_commit();

        auto pre_kv = [&](int t, int s) {
            int kv0 = t * 64;
#pragma unroll
            for (int u = 0; u < 4; u++) {
                int c = tid + u * 256;          // 0..1023
                int arr = c >> 9;               // 0=K, 1=V
                int rc = c & 511;
                int row = rc >> 3, seg = rc & 7;
                const __half* g = (arr ? g_vh : g_kh) + gb + (size_t)(kv0 + row) * DMODEL + seg * 8;
                cp16(sbase + (uint32_t)(FQ_ELE + s * FSTAGE_ELE + arr * FKV_ELE
                                        + row * FSTRIDE + seg * 8) * 2, g);
            }
        };
        pre_kv(0, 0); cp_commit();
        pre_kv(1, 1); cp_commit();

        // Q + KV tile 0 ready (KV tile 1 may still be in flight)
        cp_wait<1>();
        __syncthreads();

        // Resident Q A-fragments (4 k-steps over DH=64)
        uint32_t qa[4][4];
#pragma unroll
        for (int ks = 0; ks < 4; ks++)
            ldsm4(qa[ks], sbase + (uint32_t)((wid * 16 + (lane & 15)) * FSTRIDE
                                             + ks * 16 + (lane >> 4) * 8) * 2);

        float oacc[8][4];
#pragma unroll
        for (int j = 0; j < 8; j++)
#pragma unroll
            for (int e = 0; e < 4; e++) oacc[j][e] = 0.f;
        float l0 = 0.f, l1 = 0.f;

        const int rowlo = q0 + wid * 16;
        const int r0g = rowlo + (lane >> 2);
        const int cq = (lane & 3) * 2;

        for (int t = 0; t < n_tiles; t++) {
            if (t > 0) {
                cp_wait<1>();
                __syncthreads();   // all warps done with stage (t-1)%3; stage t%3 loaded
            }
            // prefetch into stage (t+2)%3 == (t-1)%3 (freed by the barrier above)
            if (t + 2 < n_tiles) pre_kv(t + 2, (t + 2) % 3);
            cp_commit();

            const int s = t % 3, kv0 = t * 64;
            const uint32_t kbase = sbase + (uint32_t)(FQ_ELE + s * FSTAGE_ELE) * 2;
            const uint32_t vbase = kbase + (uint32_t)FKV_ELE * 2;

            if (kv0 + 63 <= rowlo) {
                flash_half<false>(kv0,      0,  rowlo, r0g, cq, lane, kbase, vbase, qa, oacc, l0, l1);
                flash_half<false>(kv0 + 32, 32, rowlo, r0g, cq, lane, kbase, vbase, qa, oacc, l0, l1);
            } else if (kv0 <= rowlo + 15) {
                flash_half<true>(kv0, 0, rowlo, r0g, cq, lane, kbase, vbase, qa, oacc, l0, l1);
                if (kv0 + 32 <= rowlo + 15)
                    flash_half<true>(kv0 + 32, 32, rowlo, r0g, cq, lane, kbase, vbase, qa, oacc, l0, l1);
            }
        }

        // Row sums across the quad, normalize, store ctx fp16
        l0 += __shfl_xor_sync(0xffffffffu, l0, 1);
        l0 += __shfl_xor_sync(0xffffffffu, l0, 2);
        l1 += __shfl_xor_sync(0xffffffffu, l1, 1);
        l1 += __shfl_xor_sync(0xffffffffu, l1, 2);
        const float inv0 = 1.0f / l0, inv1 = 1.0f / l1;
        const size_t rA = gb + (size_t)r0g * DMODEL;
        const size_t rB = gb + (size_t)(r0g + 8) * DMODEL;
#pragma unroll
        for (int j = 0; j < 8; j++) {
            *(uint32_t*)(g_ch + rA + 8 * j + cq) = pack_h2(oacc[j][0] * inv0, oacc[j][1] * inv0);
            *(uint32_t*)(g_ch + rB + 8 * j + cq) = pack_h2(oacc[j][2] * inv1, oacc[j][3] * inv1);
        }
    }
}

// ---------------------------------------------------------------------------
extern "C" void kernel_launch(void* const* d_in, const int* in_sizes, int n_in,
                              void* d_out, int out_size)
{
    const float* x  = (const float*)d_in[0];
    const float* Wq = (const float*)d_in[1];
    const float* Wk = (const float*)d_in[2];
    const float* Wv = (const float*)d_in[3];
    const float* Wo = (const float*)d_in[4];
    const float* bo = (const float*)d_in[5];
    float* out = (float*)d_out;

    cudaFuncSetAttribute(qkv_gemm_kernel, cudaFuncAttributeMaxDynamicSharedMemorySize, GEMM_SMEM_BYTES);
    cudaFuncSetAttribute(out_gemm_kernel, cudaFuncAttributeMaxDynamicSharedMemorySize, GEMM_SMEM_BYTES);
    cudaFuncSetAttribute(flash_kernel,    cudaFuncAttributeMaxDynamicSharedMemorySize, FLASH_SMEM_BYTES);

    // 0. reset persistent work counter (inside the graph, deterministic)
    reset_ctr_kernel<<<1, 1>>>();

    // 1. x -> fp16
    xconv_kernel<<<MROWS * DMODEL / 1024, 256>>>(x);

    // 2. transpose + convert weights to fp16
    wconv_kernel<<<dim3(DMODEL / 32, DMODEL / 32, 4), dim3(32, 8)>>>(Wq, Wk, Wv, Wo);

    // 3. QKV projections (fp16 HMMA, 256x128 tiles)
    qkv_gemm_kernel<<<dim3(DMODEL / 128, MROWS / 256, 3), 256, GEMM_SMEM_BYTES>>>();

    // 4. Flash attention (fp16 HMMA, persistent LPT scheduling)
    flash_kernel<<<FLASH_GRID, 256, FLASH_SMEM_BYTES>>>();

    // 5. Output projection + bias (fp32 out)
    out_gemm_kernel<<<dim3(DMODEL / 128, MROWS / 256, 1), 256, GEMM_SMEM_BYTES>>>(bo, out);
}

// round 13
// speedup vs baseline: 1.0543x; 1.0543x over previous
#include <cuda_runtime.h>
#include <cuda_fp16.h>
#include <cstdint>

#define BBATCH 2
#define SEQ    2048
#define DMODEL 1024
#define NHEAD  16
#define DHEAD  64
#define MROWS  (BBATCH*SEQ)     // 4096

// ---------------------------------------------------------------------------
// Scratch (device globals; no allocation allowed)
// ---------------------------------------------------------------------------
__device__ __half g_wh[4*DMODEL*DMODEL];   // W^T [n][k] fp16 (q,k,v,o)
__device__ __half g_xh[MROWS*DMODEL];      // x fp16
__device__ __half g_qh[MROWS*DMODEL];
__device__ __half g_kh[MROWS*DMODEL];
__device__ __half g_vh[MROWS*DMODEL];
__device__ __half g_ch[MROWS*DMODEL];      // ctx fp16

// ---------------------------------------------------------------------------
// PTX helpers (sm_80-baseline; valid on plain sm_103 target)
// ---------------------------------------------------------------------------
__device__ __forceinline__ uint32_t smem_u32(const void* p) {
    uint32_t a;
    asm("{ .reg .u64 t; cvta.to.shared.u64 t, %1; cvt.u32.u64 %0, t; }" : "=r"(a) : "l"(p));
    return a;
}
__device__ __forceinline__ void cp16(uint32_t s, const void* g) {
    asm volatile("cp.async.cg.shared.global [%0], [%1], 16;" :: "r"(s), "l"(g));
}
__device__ __forceinline__ void cp_commit() {
    asm volatile("cp.async.commit_group;" ::: "memory");
}
template<int N> __device__ __forceinline__ void cp_wait() {
    asm volatile("cp.async.wait_group %0;" :: "n"(N) : "memory");
}
__device__ __forceinline__ void ldsm4(uint32_t* r, uint32_t a) {
    asm volatile("ldmatrix.sync.aligned.m8n8.x4.shared.b16 {%0,%1,%2,%3}, [%4];"
        : "=r"(r[0]), "=r"(r[1]), "=r"(r[2]), "=r"(r[3]) : "r"(a));
}
__device__ __forceinline__ void ldsm4t(uint32_t* r, uint32_t a) {
    asm volatile("ldmatrix.sync.aligned.m8n8.x4.trans.shared.b16 {%0,%1,%2,%3}, [%4];"
        : "=r"(r[0]), "=r"(r[1]), "=r"(r[2]), "=r"(r[3]) : "r"(a));
}
__device__ __forceinline__ void mma16816(float* c, const uint32_t* a,
                                         uint32_t b0, uint32_t b1) {
    asm volatile("mma.sync.aligned.m16n8k16.row.col.f32.f16.f16.f32 "
        "{%0,%1,%2,%3}, {%4,%5,%6,%7}, {%8,%9}, {%0,%1,%2,%3};"
        : "+f"(c[0]), "+f"(c[1]), "+f"(c[2]), "+f"(c[3])
        : "r"(a[0]), "r"(a[1]), "r"(a[2]), "r"(a[3]), "r"(b0), "r"(b1));
}
__device__ __forceinline__ uint32_t pack_h2(float a, float b) {
    __half2 h = __floats2half2_rn(a, b);
    return *reinterpret_cast<uint32_t*>(&h);
}

// FFMA-only exp2 (deg-4 poly, ~4e-5 rel err)
__device__ __forceinline__ float fexp2(float t) {
    float z = t + 12582912.0f;                 // 1.5*2^23 magic round
    int   i = __float_as_int(z) << 23;
    float f = t - (z - 12582912.0f);           // f in [-0.5, 0.5]
    float p = 0.0096181291f;
    p = fmaf(p, f, 0.0555041087f);
    p = fmaf(p, f, 0.2402265069f);
    p = fmaf(p, f, 0.6931471806f);
    p = fmaf(p, f, 1.0f);
    return __int_as_float(__float_as_int(p) + i);
}

#define K1F 0.18033688011112042f   // log2(e)/sqrt(64)

// ---------------------------------------------------------------------------
// Conversions
// ---------------------------------------------------------------------------
__global__ __launch_bounds__(256)
void xconv_kernel(const float* __restrict__ in)
{
    int i = (blockIdx.x * 256 + threadIdx.x) * 4;
    float4 v = *(const float4*)(in + i);
    uint2 u = make_uint2(pack_h2(v.x, v.y), pack_h2(v.z, v.w));
    *(uint2*)(g_xh + i) = u;
}

// Transpose W[k][n] fp32 -> W^T[n][k] fp16
__global__ __launch_bounds__(256)
void wconv_kernel(const float* __restrict__ Wq, const float* __restrict__ Wk,
                  const float* __restrict__ Wv, const float* __restrict__ Wo)
{
    __shared__ float ts[32][33];
    int z = blockIdx.z;
    const float* W = (z == 0) ? Wq : (z == 1) ? Wk : (z == 2) ? Wv : Wo;
    int n0 = blockIdx.x * 32, k0 = blockIdx.y * 32;
    int tx = threadIdx.x, ty = threadIdx.y;   // 32 x 8
#pragma unroll
    for (int j = 0; j < 4; j++)
        ts[ty + 8 * j][tx] = W[(size_t)(k0 + ty + 8 * j) * DMODEL + n0 + tx];
    __syncthreads();
    size_t wb = (size_t)z * DMODEL * DMODEL;
#pragma unroll
    for (int j = 0; j < 4; j++) {
        float v = ts[tx][ty + 8 * j];
        g_wh[wb + (size_t)(n0 + ty + 8 * j) * DMODEL + k0 + tx] = __float2half_rn(v);
    }
}

// swizzled half-offset within a row-major [rows][64] tile
__device__ __forceinline__ uint32_t gswz(int row, int seg) {
    return (uint32_t)(row * 64 + ((seg ^ (row & 7)) << 3));
}

// ---------------------------------------------------------------------------
// fp16 HMMA GEMM: C = A @ W^T (+bias).  CTA 256x128, 16 warps (4m x 4n ->
// 64x32 warp tiles), 512 threads, K-slab 64, 3-stage cp.async
// (prefetch-before-compute, one sync per slab), XOR-swizzled smem
// (48KB/stage, 144KB -> 1 CTA/SM, 16 warps/SM).
// ---------------------------------------------------------------------------
#define G2A_ELE (256*64)                    // 16384 halves
#define G2B_ELE (128*64)                    // 8192 halves
#define G2STAGE_ELE (G2A_ELE + G2B_ELE)     // 24576 halves
#define GEMM_SMEM_BYTES (3*G2STAGE_ELE*2)   // 147456

template<int MODE>   // 0: fp16 out, 1: fp32 out + bias
__device__ __forceinline__ void gemm_device(const __half* __restrict__ A,
                                            const __half* __restrict__ B,
                                            int m0, int n0,
                                            __half* __restrict__ hout,
                                            float* __restrict__ fout,
                                            const float* __restrict__ bias)
{
    extern __shared__ __half gsm[];
    const int tid = threadIdx.x;
    const int wid = tid >> 5, lane = tid & 31;
    const int wm = (wid >> 2) * 64, wn = (wid & 3) * 32;
    const uint32_t sbase = smem_u32(gsm);

    // per k-slab: A 256 rows + B 128 rows, 8 segs each = 3072 chunks / 512 thr
    auto prefetch = [&](int s, int k0) {
#pragma unroll
        for (int t = 0; t < 6; t++) {
            int c = tid + t * 512;          // 0..3071
            const __half* g;
            uint32_t abase;
            int row, seg;
            if (t < 4) {                    // A: c in 0..2047
                row = c >> 3; seg = c & 7;
                g = A + (size_t)(m0 + row) * DMODEL + k0 + seg * 8;
                abase = 0;
            } else {                        // B: c in 2048..3071
                int rc = c - 2048;
                row = rc >> 3; seg = rc & 7;
                g = B + (size_t)(n0 + row) * DMODEL + k0 + seg * 8;
                abase = G2A_ELE;
            }
            cp16(sbase + (uint32_t)(s * G2STAGE_ELE + abase) * 2 + gswz(row, seg) * 2, g);
        }
    };
    prefetch(0, 0);  cp_commit();
    prefetch(1, 64); cp_commit();

    float acc[4][4][4];
#pragma unroll
    for (int i = 0; i < 4; i++)
#pragma unroll
        for (int j = 0; j < 4; j++)
#pragma unroll
            for (int e = 0; e < 4; e++) acc[i][j][e] = 0.f;

    const int NC = DMODEL / 64;   // 16 slab iterations
    for (int c = 0; c < NC; c++) {
        cp_wait<1>();
        __syncthreads();           // all warps done with stage (c-1)%3; stage c%3 loaded

        // prefetch into stage (c+2)%3 == (c-1)%3 (freed by the barrier above)
        if (c + 2 < NC) prefetch((c + 2) % 3, (c + 2) * 64);
        cp_commit();

        const int s = c % 3;
        const uint32_t st = sbase + (uint32_t)(s * G2STAGE_ELE) * 2;

#pragma unroll
        for (int ks = 0; ks < 4; ks++) {
            uint32_t af[4][4];
#pragma unroll
            for (int mf = 0; mf < 4; mf++)
                ldsm4(af[mf], st + gswz(wm + mf * 16 + (lane & 15),
                                        2 * ks + (lane >> 4)) * 2);
#pragma unroll
            for (int p = 0; p < 2; p++) {
                uint32_t b4[4];
                ldsm4(b4, st + (uint32_t)(G2A_ELE * 2)
                          + gswz(wn + p * 16 + (lane & 15), 2 * ks + (lane >> 4)) * 2);
#pragma unroll
                for (int mf = 0; mf < 4; mf++) {
                    mma16816(acc[mf][2 * p],     af[mf], b4[0], b4[2]);
                    mma16816(acc[mf][2 * p + 1], af[mf], b4[1], b4[3]);
                }
            }
        }
    }

    const int r0 = lane >> 2, cc = (lane & 3) * 2;
#pragma unroll
    for (int mf = 0; mf < 4; mf++) {
        int m = m0 + wm + mf * 16 + r0;
#pragma unroll
        for (int nf = 0; nf < 4; nf++) {
            int n = n0 + wn + (nf >> 1) * 16 + (nf & 1) * 8 + cc;
            if (MODE == 0) {
                *(uint32_t*)(hout + (size_t)m * DMODEL + n) =
                    pack_h2(acc[mf][nf][0], acc[mf][nf][1]);
                *(uint32_t*)(hout + (size_t)(m + 8) * DMODEL + n) =
                    pack_h2(acc[mf][nf][2], acc[mf][nf][3]);
            } else {
                float b0 = bias[n], b1 = bias[n + 1];
                *(float2*)(fout + (size_t)m * DMODEL + n) =
                    make_float2(acc[mf][nf][0] + b0, acc[mf][nf][1] + b1);
                *(float2*)(fout + (size_t)(m + 8) * DMODEL + n) =
                    make_float2(acc[mf][nf][2] + b0, acc[mf][nf][3] + b1);
            }
        }
    }
}

__global__ __launch_bounds__(512, 1)
void qkv_gemm_kernel()
{
    const int z = blockIdx.z;
    __half* out = (z == 0) ? g_qh : (z == 1) ? g_kh : g_vh;
    gemm_device<0>(g_xh, g_wh + (size_t)z * DMODEL * DMODEL,
                   blockIdx.y * 256, blockIdx.x * 128, out, nullptr, nullptr);
}

__global__ __launch_bounds__(512, 1)
void out_gemm_kernel(const float* __restrict__ bo, float* __restrict__ out)
{
    gemm_device<1>(g_ch, g_wh + (size_t)3 * DMODEL * DMODEL,
                   blockIdx.y * 256, blockIdx.x * 128, nullptr, out, bo);
}

// ---------------------------------------------------------------------------
// Flash attention (R11 config — best measured): fp16 HMMA, causal,
// no-max softmax, FFMA exp2. CTA = 128 q-rows (8 warps x m16), KV tiles
// of 64, 3-stage cp.async with prefetch distance 2 and ONE sync per tile,
// stride-72 padded smem, half-tile processing, masked/unmasked paths.
// ---------------------------------------------------------------------------
#define FSTRIDE 72
#define FQ_ELE (128*FSTRIDE)        // 9216 halves
#define FKV_ELE (64*FSTRIDE)        // 4608 halves
#define FSTAGE_ELE (2*FKV_ELE)      // K + V
#define FLASH_SMEM_BYTES ((FQ_ELE + 3*FSTAGE_ELE)*2)   // 73728

template<bool MASKED>
__device__ __forceinline__ void flash_half(
    int c32, int lr32, int rowlo, int r0g, int cq, int lane,
    uint32_t kbase, uint32_t vbase,
    const uint32_t (&qa)[4][4],
    float (&oacc)[8][4], float& l0, float& l1)
{
    uint32_t pa[2][4];
    bool act2[2];

    // S = Q K^T for 2 jp sub-tiles (16 kv cols each), exp -> P
#pragma unroll
    for (int jp2 = 0; jp2 < 2; jp2++) {
        const int c16 = c32 + 16 * jp2;
        act2[jp2] = !MASKED || (c16 <= rowlo + 15);
        if (MASKED && !act2[jp2]) continue;
        float sc[2][4] = {};
        uint32_t kb[4];
        const int jrow = lr32 + 16 * jp2 + (lane & 15);
#pragma unroll
        for (int ks = 0; ks < 4; ks++) {
            ldsm4(kb, kbase + (uint32_t)(jrow * FSTRIDE + ks * 16 + (lane >> 4) * 8) * 2);
            mma16816(sc[0], qa[ks], kb[0], kb[2]);
            mma16816(sc[1], qa[ks], kb[1], kb[3]);
        }
#pragma unroll
        for (int jj = 0; jj < 2; jj++) {
            float p0, p1, p2, p3;
            if (MASKED) {
                const int cg = c16 + 8 * jj + cq;
                p0 = (cg     <= r0g    ) ? fexp2(sc[jj][0] * K1F) : 0.f;
                p1 = (cg + 1 <= r0g    ) ? fexp2(sc[jj][1] * K1F) : 0.f;
                p2 = (cg     <= r0g + 8) ? fexp2(sc[jj][2] * K1F) : 0.f;
                p3 = (cg + 1 <= r0g + 8) ? fexp2(sc[jj][3] * K1F) : 0.f;
            } else {
                p0 = fexp2(sc[jj][0] * K1F);
                p1 = fexp2(sc[jj][1] * K1F);
                p2 = fexp2(sc[jj][2] * K1F);
                p3 = fexp2(sc[jj][3] * K1F);
            }
            l0 += p0 + p1;
            l1 += p2 + p3;
            pa[jp2][2 * jj]     = pack_h2(p0, p1);
            pa[jp2][2 * jj + 1] = pack_h2(p2, p3);
        }
    }

    // O += P V (partial over this half's 32 kv rows)
#pragma unroll
    for (int jpd = 0; jpd < 4; jpd++) {
        uint32_t vb[4];
#pragma unroll
        for (int jp2 = 0; jp2 < 2; jp2++) {
            if (MASKED && !act2[jp2]) continue;
            const int vrow = lr32 + 16 * jp2 + (lane & 15);
            ldsm4t(vb, vbase + (uint32_t)(vrow * FSTRIDE + 16 * jpd + (lane >> 4) * 8) * 2);
            mma16816(oacc[2 * jpd],     pa[jp2], vb[0], vb[1]);
            mma16816(oacc[2 * jpd + 1], pa[jp2], vb[2], vb[3]);
        }
    }
}

__global__ __launch_bounds__(256, 3)
void flash_kernel()
{
    extern __shared__ __half fsm[];
    const int tid = threadIdx.x, wid = tid >> 5, lane = tid & 31;
    const int qi = (int)gridDim.x - 1 - (int)blockIdx.x;   // big tiles first
    const int h = blockIdx.y, b = blockIdx.z;
    const int q0 = qi * 128;
    const int n_tiles = 2 * qi + 2;
    const uint32_t sbase = smem_u32(fsm);
    const size_t gb = (size_t)b * SEQ * DMODEL + (size_t)h * DHEAD;

    // Q tile: 128 x 64 halves
#pragma unroll
    for (int t = 0; t < 4; t++) {
        int c = tid + t * 256;
        int row = c >> 3, seg = c & 7;
        cp16(sbase + (uint32_t)(row * FSTRIDE + seg * 8) * 2,
             g_qh + gb + (size_t)(q0 + row) * DMODEL + seg * 8);
    }
    cp_commit();

    auto pre_kv = [&](int t, int s) {
        int kv0 = t * 64;
#pragma unroll
        for (int u = 0; u < 4; u++) {
            int c = tid + u * 256;          // 0..1023
            int arr = c >> 9;               // 0=K, 1=V
            int rc = c & 511;
            int row = rc >> 3, seg = rc & 7;
            const __half* g = (arr ? g_vh : g_kh) + gb + (size_t)(kv0 + row) * DMODEL + seg * 8;
            cp16(sbase + (uint32_t)(FQ_ELE + s * FSTAGE_ELE + arr * FKV_ELE
                                    + row * FSTRIDE + seg * 8) * 2, g);
        }
    };
    pre_kv(0, 0); cp_commit();
    pre_kv(1, 1); cp_commit();

    // Q + KV tile 0 ready (KV tile 1 may still be in flight)
    cp_wait<1>();
    __syncthreads();

    // Resident Q A-fragments (4 k-steps over DH=64)
    uint32_t qa[4][4];
#pragma unroll
    for (int ks = 0; ks < 4; ks++)
        ldsm4(qa[ks], sbase + (uint32_t)((wid * 16 + (lane & 15)) * FSTRIDE
                                         + ks * 16 + (lane >> 4) * 8) * 2);

    float oacc[8][4];
#pragma unroll
    for (int j = 0; j < 8; j++)
#pragma unroll
        for (int e = 0; e < 4; e++) oacc[j][e] = 0.f;
    float l0 = 0.f, l1 = 0.f;

    const int rowlo = q0 + wid * 16;
    const int r0g = rowlo + (lane >> 2);
    const int cq = (lane & 3) * 2;

    for (int t = 0; t < n_tiles; t++) {
        if (t > 0) {
            cp_wait<1>();
            __syncthreads();       // all warps done with stage (t-1)%3; stage t%3 loaded
        }
        // prefetch into stage (t+2)%3 == (t-1)%3 (freed by the barrier above)
        if (t + 2 < n_tiles) pre_kv(t + 2, (t + 2) % 3);
        cp_commit();

        const int s = t % 3, kv0 = t * 64;
        const uint32_t kbase = sbase + (uint32_t)(FQ_ELE + s * FSTAGE_ELE) * 2;
        const uint32_t vbase = kbase + (uint32_t)FKV_ELE * 2;

        if (kv0 + 63 <= rowlo) {
            // fully visible tile: no causal masking anywhere
            flash_half<false>(kv0,      0,  rowlo, r0g, cq, lane, kbase, vbase, qa, oacc, l0, l1);
            flash_half<false>(kv0 + 32, 32, rowlo, r0g, cq, lane, kbase, vbase, qa, oacc, l0, l1);
        } else if (kv0 <= rowlo + 15) {
            // diagonal tile: masked path
            flash_half<true>(kv0, 0, rowlo, r0g, cq, lane, kbase, vbase, qa, oacc, l0, l1);
            if (kv0 + 32 <= rowlo + 15)
                flash_half<true>(kv0 + 32, 32, rowlo, r0g, cq, lane, kbase, vbase, qa, oacc, l0, l1);
        }
    }

    // Row sums across the quad, normalize, store ctx fp16
    l0 += __shfl_xor_sync(0xffffffffu, l0, 1);
    l0 += __shfl_xor_sync(0xffffffffu, l0, 2);
    l1 += __shfl_xor_sync(0xffffffffu, l1, 1);
    l1 += __shfl_xor_sync(0xffffffffu, l1, 2);
    const float inv0 = 1.0f / l0, inv1 = 1.0f / l1;
    const size_t rA = gb + (size_t)r0g * DMODEL;
    const size_t rB = gb + (size_t)(r0g + 8) * DMODEL;
#pragma unroll
    for (int j = 0; j < 8; j++) {
        *(uint32_t*)(g_ch + rA + 8 * j + cq) = pack_h2(oacc[j][0] * inv0, oacc[j][1] * inv0);
        *(uint32_t*)(g_ch + rB + 8 * j + cq) = pack_h2(oacc[j][2] * inv1, oacc[j][3] * inv1);
    }
}

// ---------------------------------------------------------------------------
extern "C" void kernel_launch(void* const* d_in, const int* in_sizes, int n_in,
                              void* d_out, int out_size)
{
    const float* x  = (const float*)d_in[0];
    const float* Wq = (const float*)d_in[1];
    const float* Wk = (const float*)d_in[2];
    const float* Wv = (const float*)d_in[3];
    const float* Wo = (const float*)d_in[4];
    const float* bo = (const float*)d_in[5];
    float* out = (float*)d_out;

    cudaFuncSetAttribute(qkv_gemm_kernel, cudaFuncAttributeMaxDynamicSharedMemorySize, GEMM_SMEM_BYTES);
    cudaFuncSetAttribute(out_gemm_kernel, cudaFuncAttributeMaxDynamicSharedMemorySize, GEMM_SMEM_BYTES);
    cudaFuncSetAttribute(flash_kernel,    cudaFuncAttributeMaxDynamicSharedMemorySize, FLASH_SMEM_BYTES);

    // 1. x -> fp16
    xconv_kernel<<<MROWS * DMODEL / 1024, 256>>>(x);

    // 2. transpose + convert weights to fp16
    wconv_kernel<<<dim3(DMODEL / 32, DMODEL / 32, 4), dim3(32, 8)>>>(Wq, Wk, Wv, Wo);

    // 3. QKV projections (fp16 HMMA, 256x128 tiles, 512 threads)
    qkv_gemm_kernel<<<dim3(DMODEL / 128, MROWS / 256, 3), 512, GEMM_SMEM_BYTES>>>();

    // 4. Flash attention (fp16 HMMA)
    flash_kernel<<<dim3(SEQ / 128, NHEAD, BBATCH), 256, FLASH_SMEM_BYTES>>>();

    // 5. Output projection + bias (fp32 out)
    out_gemm_kernel<<<dim3(DMODEL / 128, MROWS / 256, 1), 512, GEMM_SMEM_BYTES>>>(bo, out);
}

// round 14
// speedup vs baseline: 1.1232x; 1.0654x over previous
#include <cuda_runtime.h>
#include <cuda_fp16.h>
#include <cstdint>

#define BBATCH 2
#define SEQ    2048
#define DMODEL 1024
#define NHEAD  16
#define DHEAD  64
#define MROWS  (BBATCH*SEQ)     // 4096

// ---------------------------------------------------------------------------
// Scratch (device globals; no allocation allowed)
// ---------------------------------------------------------------------------
__device__ __half g_wh[4*DMODEL*DMODEL];   // W^T [n][k] fp16 (q,k,v,o)
__device__ __half g_xh[MROWS*DMODEL];      // x fp16
__device__ __half g_qh[MROWS*DMODEL];
__device__ __half g_kh[MROWS*DMODEL];
__device__ __half g_vh[MROWS*DMODEL];
__device__ __half g_ch[MROWS*DMODEL];      // ctx fp16

// ---------------------------------------------------------------------------
// PTX helpers (sm_80-baseline; valid on plain sm_103 target)
// ---------------------------------------------------------------------------
__device__ __forceinline__ uint32_t smem_u32(const void* p) {
    uint32_t a;
    asm("{ .reg .u64 t; cvta.to.shared.u64 t, %1; cvt.u32.u64 %0, t; }" : "=r"(a) : "l"(p));
    return a;
}
__device__ __forceinline__ void cp16(uint32_t s, const void* g) {
    asm volatile("cp.async.cg.shared.global [%0], [%1], 16;" :: "r"(s), "l"(g));
}
__device__ __forceinline__ void cp_commit() {
    asm volatile("cp.async.commit_group;" ::: "memory");
}
template<int N> __device__ __forceinline__ void cp_wait() {
    asm volatile("cp.async.wait_group %0;" :: "n"(N) : "memory");
}
__device__ __forceinline__ void ldsm4(uint32_t* r, uint32_t a) {
    asm volatile("ldmatrix.sync.aligned.m8n8.x4.shared.b16 {%0,%1,%2,%3}, [%4];"
        : "=r"(r[0]), "=r"(r[1]), "=r"(r[2]), "=r"(r[3]) : "r"(a));
}
__device__ __forceinline__ void ldsm4t(uint32_t* r, uint32_t a) {
    asm volatile("ldmatrix.sync.aligned.m8n8.x4.trans.shared.b16 {%0,%1,%2,%3}, [%4];"
        : "=r"(r[0]), "=r"(r[1]), "=r"(r[2]), "=r"(r[3]) : "r"(a));
}
__device__ __forceinline__ void mma16816(float* c, const uint32_t* a,
                                         uint32_t b0, uint32_t b1) {
    asm volatile("mma.sync.aligned.m16n8k16.row.col.f32.f16.f16.f32 "
        "{%0,%1,%2,%3}, {%4,%5,%6,%7}, {%8,%9}, {%0,%1,%2,%3};"
        : "+f"(c[0]), "+f"(c[1]), "+f"(c[2]), "+f"(c[3])
        : "r"(a[0]), "r"(a[1]), "r"(a[2]), "r"(a[3]), "r"(b0), "r"(b1));
}
__device__ __forceinline__ uint32_t pack_h2(float a, float b) {
    __half2 h = __floats2half2_rn(a, b);
    return *reinterpret_cast<uint32_t*>(&h);
}

// single-instruction exp2 on the MUFU pipe (err ~2^-21, negligible vs fp16)
__device__ __forceinline__ float fexp2(float t) {
    float r;
    asm("ex2.approx.f32 %0, %1;" : "=f"(r) : "f"(t));
    return r;
}

#define K1F 0.18033688011112042f   // log2(e)/sqrt(64)

// ---------------------------------------------------------------------------
// Conversions
// ---------------------------------------------------------------------------
__global__ __launch_bounds__(256)
void xconv_kernel(const float* __restrict__ in)
{
    int i = (blockIdx.x * 256 + threadIdx.x) * 4;
    float4 v = *(const float4*)(in + i);
    uint2 u = make_uint2(pack_h2(v.x, v.y), pack_h2(v.z, v.w));
    *(uint2*)(g_xh + i) = u;
}

// Transpose W[k][n] fp32 -> W^T[n][k] fp16
__global__ __launch_bounds__(256)
void wconv_kernel(const float* __restrict__ Wq, const float* __restrict__ Wk,
                  const float* __restrict__ Wv, const float* __restrict__ Wo)
{
    __shared__ float ts[32][33];
    int z = blockIdx.z;
    const float* W = (z == 0) ? Wq : (z == 1) ? Wk : (z == 2) ? Wv : Wo;
    int n0 = blockIdx.x * 32, k0 = blockIdx.y * 32;
    int tx = threadIdx.x, ty = threadIdx.y;   // 32 x 8
#pragma unroll
    for (int j = 0; j < 4; j++)
        ts[ty + 8 * j][tx] = W[(size_t)(k0 + ty + 8 * j) * DMODEL + n0 + tx];
    __syncthreads();
    size_t wb = (size_t)z * DMODEL * DMODEL;
#pragma unroll
    for (int j = 0; j < 4; j++) {
        float v = ts[tx][ty + 8 * j];
        g_wh[wb + (size_t)(n0 + ty + 8 * j) * DMODEL + k0 + tx] = __float2half_rn(v);
    }
}

// swizzled half-offset within a row-major [rows][64] tile
__device__ __forceinline__ uint32_t gswz(int row, int seg) {
    return (uint32_t)(row * 64 + ((seg ^ (row & 7)) << 3));
}

// ---------------------------------------------------------------------------
// fp16 HMMA GEMM: C = A @ W^T (+bias).  CTA 256x128, 16 warps (4m x 4n ->
// 64x32 warp tiles), 512 threads, K-slab 64, 3-stage cp.async
// (prefetch-before-compute, one sync per slab), XOR-swizzled smem
// (48KB/stage, 144KB -> 1 CTA/SM, 16 warps/SM).
// ---------------------------------------------------------------------------
#define G2A_ELE (256*64)                    // 16384 halves
#define G2B_ELE (128*64)                    // 8192 halves
#define G2STAGE_ELE (G2A_ELE + G2B_ELE)     // 24576 halves
#define GEMM_SMEM_BYTES (3*G2STAGE_ELE*2)   // 147456

template<int MODE>   // 0: fp16 out, 1: fp32 out + bias
__device__ __forceinline__ void gemm_device(const __half* __restrict__ A,
                                            const __half* __restrict__ B,
                                            int m0, int n0,
                                            __half* __restrict__ hout,
                                            float* __restrict__ fout,
                                            const float* __restrict__ bias)
{
    extern __shared__ __half gsm[];
    const int tid = threadIdx.x;
    const int wid = tid >> 5, lane = tid & 31;
    const int wm = (wid >> 2) * 64, wn = (wid & 3) * 32;
    const uint32_t sbase = smem_u32(gsm);

    // per k-slab: A 256 rows + B 128 rows, 8 segs each = 3072 chunks / 512 thr
    auto prefetch = [&](int s, int k0) {
#pragma unroll
        for (int t = 0; t < 6; t++) {
            int c = tid + t * 512;          // 0..3071
            const __half* g;
            uint32_t abase;
            int row, seg;
            if (t < 4) {                    // A: c in 0..2047
                row = c >> 3; seg = c & 7;
                g = A + (size_t)(m0 + row) * DMODEL + k0 + seg * 8;
                abase = 0;
            } else {                        // B: c in 2048..3071
                int rc = c - 2048;
                row = rc >> 3; seg = rc & 7;
                g = B + (size_t)(n0 + row) * DMODEL + k0 + seg * 8;
                abase = G2A_ELE;
            }
            cp16(sbase + (uint32_t)(s * G2STAGE_ELE + abase) * 2 + gswz(row, seg) * 2, g);
        }
    };
    prefetch(0, 0);  cp_commit();
    prefetch(1, 64); cp_commit();

    float acc[4][4][4];
#pragma unroll
    for (int i = 0; i < 4; i++)
#pragma unroll
        for (int j = 0; j < 4; j++)
#pragma unroll
            for (int e = 0; e < 4; e++) acc[i][j][e] = 0.f;

    const int NC = DMODEL / 64;   // 16 slab iterations
    for (int c = 0; c < NC; c++) {
        cp_wait<1>();
        __syncthreads();           // all warps done with stage (c-1)%3; stage c%3 loaded

        // prefetch into stage (c+2)%3 == (c-1)%3 (freed by the barrier above)
        if (c + 2 < NC) prefetch((c + 2) % 3, (c + 2) * 64);
        cp_commit();

        const int s = c % 3;
        const uint32_t st = sbase + (uint32_t)(s * G2STAGE_ELE) * 2;

#pragma unroll
        for (int ks = 0; ks < 4; ks++) {
            uint32_t af[4][4];
#pragma unroll
            for (int mf = 0; mf < 4; mf++)
                ldsm4(af[mf], st + gswz(wm + mf * 16 + (lane & 15),
                                        2 * ks + (lane >> 4)) * 2);
#pragma unroll
            for (int p = 0; p < 2; p++) {
                uint32_t b4[4];
                ldsm4(b4, st + (uint32_t)(G2A_ELE * 2)
                          + gswz(wn + p * 16 + (lane & 15), 2 * ks + (lane >> 4)) * 2);
#pragma unroll
                for (int mf = 0; mf < 4; mf++) {
                    mma16816(acc[mf][2 * p],     af[mf], b4[0], b4[2]);
                    mma16816(acc[mf][2 * p + 1], af[mf], b4[1], b4[3]);
                }
            }
        }
    }

    const int r0 = lane >> 2, cc = (lane & 3) * 2;
#pragma unroll
    for (int mf = 0; mf < 4; mf++) {
        int m = m0 + wm + mf * 16 + r0;
#pragma unroll
        for (int nf = 0; nf < 4; nf++) {
            int n = n0 + wn + (nf >> 1) * 16 + (nf & 1) * 8 + cc;
            if (MODE == 0) {
                *(uint32_t*)(hout + (size_t)m * DMODEL + n) =
                    pack_h2(acc[mf][nf][0], acc[mf][nf][1]);
                *(uint32_t*)(hout + (size_t)(m + 8) * DMODEL + n) =
                    pack_h2(acc[mf][nf][2], acc[mf][nf][3]);
            } else {
                float b0 = bias[n], b1 = bias[n + 1];
                *(float2*)(fout + (size_t)m * DMODEL + n) =
                    make_float2(acc[mf][nf][0] + b0, acc[mf][nf][1] + b1);
                *(float2*)(fout + (size_t)(m + 8) * DMODEL + n) =
                    make_float2(acc[mf][nf][2] + b0, acc[mf][nf][3] + b1);
            }
        }
    }
}

__global__ __launch_bounds__(512, 1)
void qkv_gemm_kernel()
{
    const int z = blockIdx.z;
    __half* out = (z == 0) ? g_qh : (z == 1) ? g_kh : g_vh;
    gemm_device<0>(g_xh, g_wh + (size_t)z * DMODEL * DMODEL,
                   blockIdx.y * 256, blockIdx.x * 128, out, nullptr, nullptr);
}

__global__ __launch_bounds__(512, 1)
void out_gemm_kernel(const float* __restrict__ bo, float* __restrict__ out)
{
    gemm_device<1>(g_ch, g_wh + (size_t)3 * DMODEL * DMODEL,
                   blockIdx.y * 256, blockIdx.x * 128, nullptr, out, bo);
}

// ---------------------------------------------------------------------------
// Flash attention: fp16 HMMA, causal, no-max softmax, MUFU ex2.approx.
// CTA = 128 q-rows (8 warps x m16), KV tiles of 64, 3-stage cp.async with
// prefetch distance 2 and ONE sync per tile, stride-72 padded smem,
// half-tile processing, compile-time masked/unmasked paths.
// ---------------------------------------------------------------------------
#define FSTRIDE 72
#define FQ_ELE (128*FSTRIDE)        // 9216 halves
#define FKV_ELE (64*FSTRIDE)        // 4608 halves
#define FSTAGE_ELE (2*FKV_ELE)      // K + V
#define FLASH_SMEM_BYTES ((FQ_ELE + 3*FSTAGE_ELE)*2)   // 73728

template<bool MASKED>
__device__ __forceinline__ void flash_half(
    int c32, int lr32, int rowlo, int r0g, int cq, int lane,
    uint32_t kbase, uint32_t vbase,
    const uint32_t (&qa)[4][4],
    float (&oacc)[8][4], float& l0, float& l1)
{
    uint32_t pa[2][4];
    bool act2[2];

    // S = Q K^T for 2 jp sub-tiles (16 kv cols each), exp -> P
#pragma unroll
    for (int jp2 = 0; jp2 < 2; jp2++) {
        const int c16 = c32 + 16 * jp2;
        act2[jp2] = !MASKED || (c16 <= rowlo + 15);
        if (MASKED && !act2[jp2]) continue;
        float sc[2][4] = {};
        uint32_t kb[4];
        const int jrow = lr32 + 16 * jp2 + (lane & 15);
#pragma unroll
        for (int ks = 0; ks < 4; ks++) {
            ldsm4(kb, kbase + (uint32_t)(jrow * FSTRIDE + ks * 16 + (lane >> 4) * 8) * 2);
            mma16816(sc[0], qa[ks], kb[0], kb[2]);
            mma16816(sc[1], qa[ks], kb[1], kb[3]);
        }
#pragma unroll
        for (int jj = 0; jj < 2; jj++) {
            float p0, p1, p2, p3;
            if (MASKED) {
                const int cg = c16 + 8 * jj + cq;
                p0 = (cg     <= r0g    ) ? fexp2(sc[jj][0] * K1F) : 0.f;
                p1 = (cg + 1 <= r0g    ) ? fexp2(sc[jj][1] * K1F) : 0.f;
                p2 = (cg     <= r0g + 8) ? fexp2(sc[jj][2] * K1F) : 0.f;
                p3 = (cg + 1 <= r0g + 8) ? fexp2(sc[jj][3] * K1F) : 0.f;
            } else {
                p0 = fexp2(sc[jj][0] * K1F);
                p1 = fexp2(sc[jj][1] * K1F);
                p2 = fexp2(sc[jj][2] * K1F);
                p3 = fexp2(sc[jj][3] * K1F);
            }
            l0 += p0 + p1;
            l1 += p2 + p3;
            pa[jp2][2 * jj]     = pack_h2(p0, p1);
            pa[jp2][2 * jj + 1] = pack_h2(p2, p3);
        }
    }

    // O += P V (partial over this half's 32 kv rows)
#pragma unroll
    for (int jpd = 0; jpd < 4; jpd++) {
        uint32_t vb[4];
#pragma unroll
        for (int jp2 = 0; jp2 < 2; jp2++) {
            if (MASKED && !act2[jp2]) continue;
            const int vrow = lr32 + 16 * jp2 + (lane & 15);
            ldsm4t(vb, vbase + (uint32_t)(vrow * FSTRIDE + 16 * jpd + (lane >> 4) * 8) * 2);
            mma16816(oacc[2 * jpd],     pa[jp2], vb[0], vb[1]);
            mma16816(oacc[2 * jpd + 1], pa[jp2], vb[2], vb[3]);
        }
    }
}

__global__ __launch_bounds__(256, 3)
void flash_kernel()
{
    extern __shared__ __half fsm[];
    const int tid = threadIdx.x, wid = tid >> 5, lane = tid & 31;
    const int qi = (int)gridDim.x - 1 - (int)blockIdx.x;   // big tiles first
    const int h = blockIdx.y, b = blockIdx.z;
    const int q0 = qi * 128;
    const int n_tiles = 2 * qi + 2;
    const uint32_t sbase = smem_u32(fsm);
    const size_t gb = (size_t)b * SEQ * DMODEL + (size_t)h * DHEAD;

    // Q tile: 128 x 64 halves
#pragma unroll
    for (int t = 0; t < 4; t++) {
        int c = tid + t * 256;
        int row = c >> 3, seg = c & 7;
        cp16(sbase + (uint32_t)(row * FSTRIDE + seg * 8) * 2,
             g_qh + gb + (size_t)(q0 + row) * DMODEL + seg * 8);
    }
    cp_commit();

    auto pre_kv = [&](int t, int s) {
        int kv0 = t * 64;
#pragma unroll
        for (int u = 0; u < 4; u++) {
            int c = tid + u * 256;          // 0..1023
            int arr = c >> 9;               // 0=K, 1=V
            int rc = c & 511;
            int row = rc >> 3, seg = rc & 7;
            const __half* g = (arr ? g_vh : g_kh) + gb + (size_t)(kv0 + row) * DMODEL + seg * 8;
            cp16(sbase + (uint32_t)(FQ_ELE + s * FSTAGE_ELE + arr * FKV_ELE
                                    + row * FSTRIDE + seg * 8) * 2, g);
        }
    };
    pre_kv(0, 0); cp_commit();
    pre_kv(1, 1); cp_commit();

    // Q + KV tile 0 ready (KV tile 1 may still be in flight)
    cp_wait<1>();
    __syncthreads();

    // Resident Q A-fragments (4 k-steps over DH=64)
    uint32_t qa[4][4];
#pragma unroll
    for (int ks = 0; ks < 4; ks++)
        ldsm4(qa[ks], sbase + (uint32_t)((wid * 16 + (lane & 15)) * FSTRIDE
                                         + ks * 16 + (lane >> 4) * 8) * 2);

    float oacc[8][4];
#pragma unroll
    for (int j = 0; j < 8; j++)
#pragma unroll
        for (int e = 0; e < 4; e++) oacc[j][e] = 0.f;
    float l0 = 0.f, l1 = 0.f;

    const int rowlo = q0 + wid * 16;
    const int r0g = rowlo + (lane >> 2);
    const int cq = (lane & 3) * 2;

    for (int t = 0; t < n_tiles; t++) {
        if (t > 0) {
            cp_wait<1>();
            __syncthreads();       // all warps done with stage (t-1)%3; stage t%3 loaded
        }
        // prefetch into stage (t+2)%3 == (t-1)%3 (freed by the barrier above)
        if (t + 2 < n_tiles) pre_kv(t + 2, (t + 2) % 3);
        cp_commit();

        const int s = t % 3, kv0 = t * 64;
        const uint32_t kbase = sbase + (uint32_t)(FQ_ELE + s * FSTAGE_ELE) * 2;
        const uint32_t vbase = kbase + (uint32_t)FKV_ELE * 2;

        if (kv0 + 63 <= rowlo) {
            // fully visible tile: no causal masking anywhere
            flash_half<false>(kv0,      0,  rowlo, r0g, cq, lane, kbase, vbase, qa, oacc, l0, l1);
            flash_half<false>(kv0 + 32, 32, rowlo, r0g, cq, lane, kbase, vbase, qa, oacc, l0, l1);
        } else if (kv0 <= rowlo + 15) {
            // diagonal tile: masked path
            flash_half<true>(kv0, 0, rowlo, r0g, cq, lane, kbase, vbase, qa, oacc, l0, l1);
            if (kv0 + 32 <= rowlo + 15)
                flash_half<true>(kv0 + 32, 32, rowlo, r0g, cq, lane, kbase, vbase, qa, oacc, l0, l1);
        }
    }

    // Row sums across the quad, normalize, store ctx fp16
    l0 += __shfl_xor_sync(0xffffffffu, l0, 1);
    l0 += __shfl_xor_sync(0xffffffffu, l0, 2);
    l1 += __shfl_xor_sync(0xffffffffu, l1, 1);
    l1 += __shfl_xor_sync(0xffffffffu, l1, 2);
    const float inv0 = 1.0f / l0, inv1 = 1.0f / l1;
    const size_t rA = gb + (size_t)r0g * DMODEL;
    const size_t rB = gb + (size_t)(r0g + 8) * DMODEL;
#pragma unroll
    for (int j = 0; j < 8; j++) {
        *(uint32_t*)(g_ch + rA + 8 * j + cq) = pack_h2(oacc[j][0] * inv0, oacc[j][1] * inv0);
        *(uint32_t*)(g_ch + rB + 8 * j + cq) = pack_h2(oacc[j][2] * inv1, oacc[j][3] * inv1);
    }
}

// ---------------------------------------------------------------------------
extern "C" void kernel_launch(void* const* d_in, const int* in_sizes, int n_in,
                              void* d_out, int out_size)
{
    const float* x  = (const float*)d_in[0];
    const float* Wq = (const float*)d_in[1];
    const float* Wk = (const float*)d_in[2];
    const float* Wv = (const float*)d_in[3];
    const float* Wo = (const float*)d_in[4];
    const float* bo = (const float*)d_in[5];
    float* out = (float*)d_out;

    cudaFuncSetAttribute(qkv_gemm_kernel, cudaFuncAttributeMaxDynamicSharedMemorySize, GEMM_SMEM_BYTES);
    cudaFuncSetAttribute(out_gemm_kernel, cudaFuncAttributeMaxDynamicSharedMemorySize, GEMM_SMEM_BYTES);
    cudaFuncSetAttribute(flash_kernel,    cudaFuncAttributeMaxDynamicSharedMemorySize, FLASH_SMEM_BYTES);

    // 1. x -> fp16
    xconv_kernel<<<MROWS * DMODEL / 1024, 256>>>(x);

    // 2. transpose + convert weights to fp16
    wconv_kernel<<<dim3(DMODEL / 32, DMODEL / 32, 4), dim3(32, 8)>>>(Wq, Wk, Wv, Wo);

    // 3. QKV projections (fp16 HMMA, 256x128 tiles, 512 threads)
    qkv_gemm_kernel<<<dim3(DMODEL / 128, MROWS / 256, 3), 512, GEMM_SMEM_BYTES>>>();

    // 4. Flash attention (fp16 HMMA, MUFU exp)
    flash_kernel<<<dim3(SEQ / 128, NHEAD, BBATCH), 256, FLASH_SMEM_BYTES>>>();

    // 5. Output projection + bias (fp32 out)
    out_gemm_kernel<<<dim3(DMODEL / 128, MROWS / 256, 1), 512, GEMM_SMEM_BYTES>>>(bo, out);
}

// round 16
// speedup vs baseline: 1.1237x; 1.0004x over previous
#include <cuda_runtime.h>
#include <cuda_fp16.h>
#include <cstdint>

#define BBATCH 2
#define SEQ    2048
#define DMODEL 1024
#define NHEAD  16
#define DHEAD  64
#define MROWS  (BBATCH*SEQ)     // 4096

// ---------------------------------------------------------------------------
// Scratch (device globals; no allocation allowed)
// ---------------------------------------------------------------------------
__device__ __half g_wh[4*DMODEL*DMODEL];   // W^T [n][k] fp16 (q,k,v,o)
__device__ __half g_xh[MROWS*DMODEL];      // x fp16
__device__ __half g_qh[MROWS*DMODEL];
__device__ __half g_kh[MROWS*DMODEL];
__device__ __half g_vh[MROWS*DMODEL];
__device__ __half g_ch[MROWS*DMODEL];      // ctx fp16

// ---------------------------------------------------------------------------
// PTX helpers (sm_80-baseline; valid on plain sm_103 target)
// ---------------------------------------------------------------------------
__device__ __forceinline__ uint32_t smem_u32(const void* p) {
    uint32_t a;
    asm("{ .reg .u64 t; cvta.to.shared.u64 t, %1; cvt.u32.u64 %0, t; }" : "=r"(a) : "l"(p));
    return a;
}
__device__ __forceinline__ void cp16(uint32_t s, const void* g) {
    asm volatile("cp.async.cg.shared.global [%0], [%1], 16;" :: "r"(s), "l"(g));
}
__device__ __forceinline__ void cp_commit() {
    asm volatile("cp.async.commit_group;" ::: "memory");
}
template<int N> __device__ __forceinline__ void cp_wait() {
    asm volatile("cp.async.wait_group %0;" :: "n"(N) : "memory");
}
__device__ __forceinline__ void ldsm4(uint32_t* r, uint32_t a) {
    asm volatile("ldmatrix.sync.aligned.m8n8.x4.shared.b16 {%0,%1,%2,%3}, [%4];"
        : "=r"(r[0]), "=r"(r[1]), "=r"(r[2]), "=r"(r[3]) : "r"(a));
}
__device__ __forceinline__ void ldsm4t(uint32_t* r, uint32_t a) {
    asm volatile("ldmatrix.sync.aligned.m8n8.x4.trans.shared.b16 {%0,%1,%2,%3}, [%4];"
        : "=r"(r[0]), "=r"(r[1]), "=r"(r[2]), "=r"(r[3]) : "r"(a));
}
__device__ __forceinline__ void mma16816(float* c, const uint32_t* a,
                                         uint32_t b0, uint32_t b1) {
    asm volatile("mma.sync.aligned.m16n8k16.row.col.f32.f16.f16.f32 "
        "{%0,%1,%2,%3}, {%4,%5,%6,%7}, {%8,%9}, {%0,%1,%2,%3};"
        : "+f"(c[0]), "+f"(c[1]), "+f"(c[2]), "+f"(c[3])
        : "r"(a[0]), "r"(a[1]), "r"(a[2]), "r"(a[3]), "r"(b0), "r"(b1));
}
__device__ __forceinline__ uint32_t pack_h2(float a, float b) {
    __half2 h = __floats2half2_rn(a, b);
    return *reinterpret_cast<uint32_t*>(&h);
}

// single-instruction exp2 on the MUFU pipe (err ~2^-21, negligible vs fp16)
__device__ __forceinline__ float fexp2(float t) {
    float r;
    asm("ex2.approx.f32 %0, %1;" : "=f"(r) : "f"(t));
    return r;
}

#define K1F 0.18033688011112042f   // log2(e)/sqrt(64)

// ---------------------------------------------------------------------------
// Conversions
// ---------------------------------------------------------------------------
__global__ __launch_bounds__(256)
void xconv_kernel(const float* __restrict__ in)
{
    int i = (blockIdx.x * 256 + threadIdx.x) * 4;
    float4 v = *(const float4*)(in + i);
    uint2 u = make_uint2(pack_h2(v.x, v.y), pack_h2(v.z, v.w));
    *(uint2*)(g_xh + i) = u;
}

// Transpose W[k][n] fp32 -> W^T[n][k] fp16
__global__ __launch_bounds__(256)
void wconv_kernel(const float* __restrict__ Wq, const float* __restrict__ Wk,
                  const float* __restrict__ Wv, const float* __restrict__ Wo)
{
    __shared__ float ts[32][33];
    int z = blockIdx.z;
    const float* W = (z == 0) ? Wq : (z == 1) ? Wk : (z == 2) ? Wv : Wo;
    int n0 = blockIdx.x * 32, k0 = blockIdx.y * 32;
    int tx = threadIdx.x, ty = threadIdx.y;   // 32 x 8
#pragma unroll
    for (int j = 0; j < 4; j++)
        ts[ty + 8 * j][tx] = W[(size_t)(k0 + ty + 8 * j) * DMODEL + n0 + tx];
    __syncthreads();
    size_t wb = (size_t)z * DMODEL * DMODEL;
#pragma unroll
    for (int j = 0; j < 4; j++) {
        float v = ts[tx][ty + 8 * j];
        g_wh[wb + (size_t)(n0 + ty + 8 * j) * DMODEL + k0 + tx] = __float2half_rn(v);
    }
}

// swizzled half-offset within a row-major [rows][64] tile
__device__ __forceinline__ uint32_t gswz(int row, int seg) {
    return (uint32_t)(row * 64 + ((seg ^ (row & 7)) << 3));
}

// ---------------------------------------------------------------------------
// fp16 HMMA GEMM: C = A @ W^T (+bias).  CTA 256x128, 8 warps (4m x 2n ->
// 64x64 warp tiles), 256 threads, K-slab 64, 3-stage cp.async (one sync
// per slab), XOR-swizzled smem (48KB/stage, 144KB -> 1 CTA/SM).
// Register double-buffered fragments across ks steps (R12 skeleton).
// ---------------------------------------------------------------------------
#define G2A_ELE (256*64)                    // 16384 halves
#define G2B_ELE (128*64)                    // 8192 halves
#define G2STAGE_ELE (G2A_ELE + G2B_ELE)     // 24576 halves
#define GEMM_SMEM_BYTES (3*G2STAGE_ELE*2)   // 147456

template<int MODE>   // 0: fp16 out, 1: fp32 out + bias
__device__ __forceinline__ void gemm_device(const __half* __restrict__ A,
                                            const __half* __restrict__ B,
                                            int m0, int n0,
                                            __half* __restrict__ hout,
                                            float* __restrict__ fout,
                                            const float* __restrict__ bias)
{
    extern __shared__ __half gsm[];
    const int tid = threadIdx.x;
    const int wid = tid >> 5, lane = tid & 31;
    const int wm = (wid >> 1) * 64, wn = (wid & 1) * 64;
    const uint32_t sbase = smem_u32(gsm);

    // per k-slab: A 256 rows + B 128 rows, 8 segs each = 3072 chunks / 256 thr
    auto prefetch = [&](int s, int k0) {
#pragma unroll
        for (int t = 0; t < 12; t++) {
            int c = tid + t * 256;          // 0..3071
            const __half* g;
            uint32_t abase;
            int row, seg;
            if (t < 8) {                    // A: c in 0..2047
                row = c >> 3; seg = c & 7;
                g = A + (size_t)(m0 + row) * DMODEL + k0 + seg * 8;
                abase = 0;
            } else {                        // B: c in 2048..3071
                int rc = c - 2048;
                row = rc >> 3; seg = rc & 7;
                g = B + (size_t)(n0 + row) * DMODEL + k0 + seg * 8;
                abase = G2A_ELE;
            }
            cp16(sbase + (uint32_t)(s * G2STAGE_ELE + abase) * 2 + gswz(row, seg) * 2, g);
        }
    };
    prefetch(0, 0);  cp_commit();
    prefetch(1, 64); cp_commit();

    float acc[4][8][4];
#pragma unroll
    for (int i = 0; i < 4; i++)
#pragma unroll
        for (int j = 0; j < 8; j++)
#pragma unroll
            for (int e = 0; e < 4; e++) acc[i][j][e] = 0.f;

    // double-buffered register fragments (full warp tile: 4 m-frags, 4 b-pairs)
    uint32_t af[2][4][4], b4[2][4][4];

    const int NC = DMODEL / 64;   // 16 slab iterations
    for (int c = 0; c < NC; c++) {
        cp_wait<1>();
        __syncthreads();           // all warps done with stage (c-1)%3; stage c%3 loaded

        // prefetch into stage (c+2)%3 == (c-1)%3 (freed by the barrier above)
        if (c + 2 < NC) prefetch((c + 2) % 3, (c + 2) * 64);
        cp_commit();

        const int s = c % 3;
        const uint32_t st = sbase + (uint32_t)(s * G2STAGE_ELE) * 2;

        auto ldfrag = [&](int buf, int ks) {
#pragma unroll
            for (int mf = 0; mf < 4; mf++)
                ldsm4(af[buf][mf], st + gswz(wm + mf * 16 + (lane & 15),
                                             2 * ks + (lane >> 4)) * 2);
#pragma unroll
            for (int p = 0; p < 4; p++)
                ldsm4(b4[buf][p], st + (uint32_t)(G2A_ELE * 2)
                          + gswz(wn + p * 16 + (lane & 15), 2 * ks + (lane >> 4)) * 2);
        };

        ldfrag(0, 0);
#pragma unroll
        for (int ks = 0; ks < 4; ks++) {
            const int cur = ks & 1, nxt = cur ^ 1;
            if (ks < 3) ldfrag(nxt, ks + 1);   // hide LDS latency under MMAs below
#pragma unroll
            for (int p = 0; p < 4; p++)
#pragma unroll
                for (int mf = 0; mf < 4; mf++) {
                    mma16816(acc[mf][2 * p],     af[cur][mf], b4[cur][p][0], b4[cur][p][2]);
                    mma16816(acc[mf][2 * p + 1], af[cur][mf], b4[cur][p][1], b4[cur][p][3]);
                }
        }
    }

    // epilogue: acc[mf][2p+jj] holds cols wn + p*16 + jj*8 (R12 mapping)
    const int r0 = lane >> 2, cc = (lane & 3) * 2;
#pragma unroll
    for (int mf = 0; mf < 4; mf++) {
        int m = m0 + wm + mf * 16 + r0;
#pragma unroll
        for (int nf = 0; nf < 8; nf++) {
            int n = n0 + wn + (nf >> 1) * 16 + (nf & 1) * 8 + cc;
            float* a = acc[mf][nf];
            if (MODE == 0) {
                *(uint32_t*)(hout + (size_t)m * DMODEL + n) = pack_h2(a[0], a[1]);
                *(uint32_t*)(hout + (size_t)(m + 8) * DMODEL + n) = pack_h2(a[2], a[3]);
            } else {
                float b0 = bias[n], b1 = bias[n + 1];
                *(float2*)(fout + (size_t)m * DMODEL + n) = make_float2(a[0] + b0, a[1] + b1);
                *(float2*)(fout + (size_t)(m + 8) * DMODEL + n) = make_float2(a[2] + b0, a[3] + b1);
            }
        }
    }
}

__global__ __launch_bounds__(256, 1)
void qkv_gemm_kernel()
{
    const int z = blockIdx.z;
    __half* out = (z == 0) ? g_qh : (z == 1) ? g_kh : g_vh;
    gemm_device<0>(g_xh, g_wh + (size_t)z * DMODEL * DMODEL,
                   blockIdx.y * 256, blockIdx.x * 128, out, nullptr, nullptr);
}

__global__ __launch_bounds__(256, 1)
void out_gemm_kernel(const float* __restrict__ bo, float* __restrict__ out)
{
    gemm_device<1>(g_ch, g_wh + (size_t)3 * DMODEL * DMODEL,
                   blockIdx.y * 256, blockIdx.x * 128, nullptr, out, bo);
}

// ---------------------------------------------------------------------------
// Flash attention (R14 config — best measured): fp16 HMMA, causal,
// no-max softmax, MUFU ex2.approx. CTA = 128 q-rows (8 warps x m16),
// KV tiles of 64, 3-stage cp.async, one sync per tile, stride-72 smem,
// half-tile processing, masked/unmasked paths.
// ---------------------------------------------------------------------------
#define FSTRIDE 72
#define FQ_ELE (128*FSTRIDE)        // 9216 halves
#define FKV_ELE (64*FSTRIDE)        // 4608 halves
#define FSTAGE_ELE (2*FKV_ELE)      // K + V
#define FLASH_SMEM_BYTES ((FQ_ELE + 3*FSTAGE_ELE)*2)   // 73728

template<bool MASKED>
__device__ __forceinline__ void flash_half(
    int c32, int lr32, int rowlo, int r0g, int cq, int lane,
    uint32_t kbase, uint32_t vbase,
    const uint32_t (&qa)[4][4],
    float (&oacc)[8][4], float& l0, float& l1)
{
    uint32_t pa[2][4];
    bool act2[2];

    // S = Q K^T for 2 jp sub-tiles (16 kv cols each), exp -> P
#pragma unroll
    for (int jp2 = 0; jp2 < 2; jp2++) {
        const int c16 = c32 + 16 * jp2;
        act2[jp2] = !MASKED || (c16 <= rowlo + 15);
        if (MASKED && !act2[jp2]) continue;
        float sc[2][4] = {};
        uint32_t kb[4];
        const int jrow = lr32 + 16 * jp2 + (lane & 15);
#pragma unroll
        for (int ks = 0; ks < 4; ks++) {
            ldsm4(kb, kbase + (uint32_t)(jrow * FSTRIDE + ks * 16 + (lane >> 4) * 8) * 2);
            mma16816(sc[0], qa[ks], kb[0], kb[2]);
            mma16816(sc[1], qa[ks], kb[1], kb[3]);
        }
#pragma unroll
        for (int jj = 0; jj < 2; jj++) {
            float p0, p1, p2, p3;
            if (MASKED) {
                const int cg = c16 + 8 * jj + cq;
                p0 = (cg     <= r0g    ) ? fexp2(sc[jj][0] * K1F) : 0.f;
                p1 = (cg + 1 <= r0g    ) ? fexp2(sc[jj][1] * K1F) : 0.f;
                p2 = (cg     <= r0g + 8) ? fexp2(sc[jj][2] * K1F) : 0.f;
                p3 = (cg + 1 <= r0g + 8) ? fexp2(sc[jj][3] * K1F) : 0.f;
            } else {
                p0 = fexp2(sc[jj][0] * K1F);
                p1 = fexp2(sc[jj][1] * K1F);
                p2 = fexp2(sc[jj][2] * K1F);
                p3 = fexp2(sc[jj][3] * K1F);
            }
            l0 += p0 + p1;
            l1 += p2 + p3;
            pa[jp2][2 * jj]     = pack_h2(p0, p1);
            pa[jp2][2 * jj + 1] = pack_h2(p2, p3);
        }
    }

    // O += P V (partial over this half's 32 kv rows)
#pragma unroll
    for (int jpd = 0; jpd < 4; jpd++) {
        uint32_t vb[4];
#pragma unroll
        for (int jp2 = 0; jp2 < 2; jp2++) {
            if (MASKED && !act2[jp2]) continue;
            const int vrow = lr32 + 16 * jp2 + (lane & 15);
            ldsm4t(vb, vbase + (uint32_t)(vrow * FSTRIDE + 16 * jpd + (lane >> 4) * 8) * 2);
            mma16816(oacc[2 * jpd],     pa[jp2], vb[0], vb[1]);
            mma16816(oacc[2 * jpd + 1], pa[jp2], vb[2], vb[3]);
        }
    }
}

__global__ __launch_bounds__(256, 3)
void flash_kernel()
{
    extern __shared__ __half fsm[];
    const int tid = threadIdx.x, wid = tid >> 5, lane = tid & 31;
    const int qi = (int)gridDim.x - 1 - (int)blockIdx.x;   // big tiles first
    const int h = blockIdx.y, b = blockIdx.z;
    const int q0 = qi * 128;
    const int n_tiles = 2 * qi + 2;
    const uint32_t sbase = smem_u32(fsm);
    const size_t gb = (size_t)b * SEQ * DMODEL + (size_t)h * DHEAD;

    // Q tile: 128 x 64 halves
#pragma unroll
    for (int t = 0; t < 4; t++) {
        int c = tid + t * 256;
        int row = c >> 3, seg = c & 7;
        cp16(sbase + (uint32_t)(row * FSTRIDE + seg * 8) * 2,
             g_qh + gb + (size_t)(q0 + row) * DMODEL + seg * 8);
    }
    cp_commit();

    auto pre_kv = [&](int t, int s) {
        int kv0 = t * 64;
#pragma unroll
        for (int u = 0; u < 4; u++) {
            int c = tid + u * 256;          // 0..1023
            int arr = c >> 9;               // 0=K, 1=V
            int rc = c & 511;
            int row = rc >> 3, seg = rc & 7;
            const __half* g = (arr ? g_vh : g_kh) + gb + (size_t)(kv0 + row) * DMODEL + seg * 8;
            cp16(sbase + (uint32_t)(FQ_ELE + s * FSTAGE_ELE + arr * FKV_ELE
                                    + row * FSTRIDE + seg * 8) * 2, g);
        }
    };
    pre_kv(0, 0); cp_commit();
    pre_kv(1, 1); cp_commit();

    // Q + KV tile 0 ready (KV tile 1 may still be in flight)
    cp_wait<1>();
    __syncthreads();

    // Resident Q A-fragments (4 k-steps over DH=64)
    uint32_t qa[4][4];
#pragma unroll
    for (int ks = 0; ks < 4; ks++)
        ldsm4(qa[ks], sbase + (uint32_t)((wid * 16 + (lane & 15)) * FSTRIDE
                                         + ks * 16 + (lane >> 4) * 8) * 2);

    float oacc[8][4];
#pragma unroll
    for (int j = 0; j < 8; j++)
#pragma unroll
        for (int e = 0; e < 4; e++) oacc[j][e] = 0.f;
    float l0 = 0.f, l1 = 0.f;

    const int rowlo = q0 + wid * 16;
    const int r0g = rowlo + (lane >> 2);
    const int cq = (lane & 3) * 2;

    for (int t = 0; t < n_tiles; t++) {
        if (t > 0) {
            cp_wait<1>();
            __syncthreads();       // all warps done with stage (t-1)%3; stage t%3 loaded
        }
        // prefetch into stage (t+2)%3 == (t-1)%3 (freed by the barrier above)
        if (t + 2 < n_tiles) pre_kv(t + 2, (t + 2) % 3);
        cp_commit();

        const int s = t % 3, kv0 = t * 64;
        const uint32_t kbase = sbase + (uint32_t)(FQ_ELE + s * FSTAGE_ELE) * 2;
        const uint32_t vbase = kbase + (uint32_t)FKV_ELE * 2;

        if (kv0 + 63 <= rowlo) {
            // fully visible tile: no causal masking anywhere
            flash_half<false>(kv0,      0,  rowlo, r0g, cq, lane, kbase, vbase, qa, oacc, l0, l1);
            flash_half<false>(kv0 + 32, 32, rowlo, r0g, cq, lane, kbase, vbase, qa, oacc, l0, l1);
        } else if (kv0 <= rowlo + 15) {
            // diagonal tile: masked path
            flash_half<true>(kv0, 0, rowlo, r0g, cq, lane, kbase, vbase, qa, oacc, l0, l1);
            if (kv0 + 32 <= rowlo + 15)
                flash_half<true>(kv0 + 32, 32, rowlo, r0g, cq, lane, kbase, vbase, qa, oacc, l0, l1);
        }
    }

    // Row sums across the quad, normalize, store ctx fp16
    l0 += __shfl_xor_sync(0xffffffffu, l0, 1);
    l0 += __shfl_xor_sync(0xffffffffu, l0, 2);
    l1 += __shfl_xor_sync(0xffffffffu, l1, 1);
    l1 += __shfl_xor_sync(0xffffffffu, l1, 2);
    const float inv0 = 1.0f / l0, inv1 = 1.0f / l1;
    const size_t rA = gb + (size_t)r0g * DMODEL;
    const size_t rB = gb + (size_t)(r0g + 8) * DMODEL;
#pragma unroll
    for (int j = 0; j < 8; j++) {
        *(uint32_t*)(g_ch + rA + 8 * j + cq) = pack_h2(oacc[j][0] * inv0, oacc[j][1] * inv0);
        *(uint32_t*)(g_ch + rB + 8 * j + cq) = pack_h2(oacc[j][2] * inv1, oacc[j][3] * inv1);
    }
}

// ---------------------------------------------------------------------------
extern "C" void kernel_launch(void* const* d_in, const int* in_sizes, int n_in,
                              void* d_out, int out_size)
{
    const float* x  = (const float*)d_in[0];
    const float* Wq = (const float*)d_in[1];
    const float* Wk = (const float*)d_in[2];
    const float* Wv = (const float*)d_in[3];
    const float* Wo = (const float*)d_in[4];
    const float* bo = (const float*)d_in[5];
    float* out = (float*)d_out;

    cudaFuncSetAttribute(qkv_gemm_kernel, cudaFuncAttributeMaxDynamicSharedMemorySize, GEMM_SMEM_BYTES);
    cudaFuncSetAttribute(out_gemm_kernel, cudaFuncAttributeMaxDynamicSharedMemorySize, GEMM_SMEM_BYTES);
    cudaFuncSetAttribute(flash_kernel,    cudaFuncAttributeMaxDynamicSharedMemorySize, FLASH_SMEM_BYTES);

    // 1. x -> fp16
    xconv_kernel<<<MROWS * DMODEL / 1024, 256>>>(x);

    // 2. transpose + convert weights to fp16
    wconv_kernel<<<dim3(DMODEL / 32, DMODEL / 32, 4), dim3(32, 8)>>>(Wq, Wk, Wv, Wo);

    // 3. QKV projections (fp16 HMMA, 256x128 tiles, frag double-buffering)
    qkv_gemm_kernel<<<dim3(DMODEL / 128, MROWS / 256, 3), 256, GEMM_SMEM_BYTES>>>();

    // 4. Flash attention (fp16 HMMA, MUFU exp)
    flash_kernel<<<dim3(SEQ / 128, NHEAD, BBATCH), 256, FLASH_SMEM_BYTES>>>();

    // 5. Output projection + bias (fp32 out)
    out_gemm_kernel<<<dim3(DMODEL / 128, MROWS / 256, 1), 256, GEMM_SMEM_BYTES>>>(bo, out);
}

// round 17
// speedup vs baseline: 1.1532x; 1.0262x over previous
#include <cuda_runtime.h>
#include <cuda_fp16.h>
#include <cstdint>

#define BBATCH 2
#define SEQ    2048
#define DMODEL 1024
#define NHEAD  16
#define DHEAD  64
#define MROWS  (BBATCH*SEQ)     // 4096

// ---------------------------------------------------------------------------
// Scratch (device globals; no allocation allowed)
// ---------------------------------------------------------------------------
__device__ __half g_wh[4*DMODEL*DMODEL];   // W^T [n][k] fp16 (q,k,v,o)
__device__ __half g_xh[MROWS*DMODEL];      // x fp16
__device__ __half g_qh[MROWS*DMODEL];
__device__ __half g_kh[MROWS*DMODEL];
__device__ __half g_vh[MROWS*DMODEL];
__device__ __half g_ch[MROWS*DMODEL];      // ctx fp16

// ---------------------------------------------------------------------------
// PTX helpers (sm_80-baseline; valid on plain sm_103 target)
// ---------------------------------------------------------------------------
__device__ __forceinline__ uint32_t smem_u32(const void* p) {
    uint32_t a;
    asm("{ .reg .u64 t; cvta.to.shared.u64 t, %1; cvt.u32.u64 %0, t; }" : "=r"(a) : "l"(p));
    return a;
}
__device__ __forceinline__ void cp16(uint32_t s, const void* g) {
    asm volatile("cp.async.cg.shared.global [%0], [%1], 16;" :: "r"(s), "l"(g));
}
__device__ __forceinline__ void cp_commit() {
    asm volatile("cp.async.commit_group;" ::: "memory");
}
template<int N> __device__ __forceinline__ void cp_wait() {
    asm volatile("cp.async.wait_group %0;" :: "n"(N) : "memory");
}
__device__ __forceinline__ void ldsm4(uint32_t* r, uint32_t a) {
    asm volatile("ldmatrix.sync.aligned.m8n8.x4.shared.b16 {%0,%1,%2,%3}, [%4];"
        : "=r"(r[0]), "=r"(r[1]), "=r"(r[2]), "=r"(r[3]) : "r"(a));
}
__device__ __forceinline__ void ldsm4t(uint32_t* r, uint32_t a) {
    asm volatile("ldmatrix.sync.aligned.m8n8.x4.trans.shared.b16 {%0,%1,%2,%3}, [%4];"
        : "=r"(r[0]), "=r"(r[1]), "=r"(r[2]), "=r"(r[3]) : "r"(a));
}
__device__ __forceinline__ void mma16816(float* c, const uint32_t* a,
                                         uint32_t b0, uint32_t b1) {
    asm volatile("mma.sync.aligned.m16n8k16.row.col.f32.f16.f16.f32 "
        "{%0,%1,%2,%3}, {%4,%5,%6,%7}, {%8,%9}, {%0,%1,%2,%3};"
        : "+f"(c[0]), "+f"(c[1]), "+f"(c[2]), "+f"(c[3])
        : "r"(a[0]), "r"(a[1]), "r"(a[2]), "r"(a[3]), "r"(b0), "r"(b1));
}
__device__ __forceinline__ uint32_t pack_h2(float a, float b) {
    __half2 h = __floats2half2_rn(a, b);
    return *reinterpret_cast<uint32_t*>(&h);
}

// single-instruction exp2 on the MUFU pipe (err ~2^-21, negligible vs fp16)
__device__ __forceinline__ float fexp2(float t) {
    float r;
    asm("ex2.approx.f32 %0, %1;" : "=f"(r) : "f"(t));
    return r;
}

#define K1F 0.18033688011112042f   // log2(e)/sqrt(64)

// ---------------------------------------------------------------------------
// Conversions
// ---------------------------------------------------------------------------
__global__ __launch_bounds__(256)
void xconv_kernel(const float* __restrict__ in)
{
    int i = (blockIdx.x * 256 + threadIdx.x) * 4;
    float4 v = *(const float4*)(in + i);
    uint2 u = make_uint2(pack_h2(v.x, v.y), pack_h2(v.z, v.w));
    *(uint2*)(g_xh + i) = u;
}

// Transpose W[k][n] fp32 -> W^T[n][k] fp16
__global__ __launch_bounds__(256)
void wconv_kernel(const float* __restrict__ Wq, const float* __restrict__ Wk,
                  const float* __restrict__ Wv, const float* __restrict__ Wo)
{
    __shared__ float ts[32][33];
    int z = blockIdx.z;
    const float* W = (z == 0) ? Wq : (z == 1) ? Wk : (z == 2) ? Wv : Wo;
    int n0 = blockIdx.x * 32, k0 = blockIdx.y * 32;
    int tx = threadIdx.x, ty = threadIdx.y;   // 32 x 8
#pragma unroll
    for (int j = 0; j < 4; j++)
        ts[ty + 8 * j][tx] = W[(size_t)(k0 + ty + 8 * j) * DMODEL + n0 + tx];
    __syncthreads();
    size_t wb = (size_t)z * DMODEL * DMODEL;
#pragma unroll
    for (int j = 0; j < 4; j++) {
        float v = ts[tx][ty + 8 * j];
        g_wh[wb + (size_t)(n0 + ty + 8 * j) * DMODEL + k0 + tx] = __float2half_rn(v);
    }
}

// swizzled half-offset within a row-major [rows][64] tile
__device__ __forceinline__ uint32_t gswz(int row, int seg) {
    return (uint32_t)(row * 64 + ((seg ^ (row & 7)) << 3));
}

// ---------------------------------------------------------------------------
// fp16 HMMA GEMM (R16 config): C = A @ W^T (+bias). CTA 256x128, 8 warps
// (4m x 2n -> 64x64 warp tiles), K-slab 64, 3-stage cp.async, one sync per
// slab, XOR-swizzled smem (48KB/stage, 144KB -> 1 CTA/SM), frag dbl-buffer.
// ---------------------------------------------------------------------------
#define G2A_ELE (256*64)                    // 16384 halves
#define G2B_ELE (128*64)                    // 8192 halves
#define G2STAGE_ELE (G2A_ELE + G2B_ELE)     // 24576 halves
#define GEMM_SMEM_BYTES (3*G2STAGE_ELE*2)   // 147456

template<int MODE>   // 0: fp16 out, 1: fp32 out + bias
__device__ __forceinline__ void gemm_device(const __half* __restrict__ A,
                                            const __half* __restrict__ B,
                                            int m0, int n0,
                                            __half* __restrict__ hout,
                                            float* __restrict__ fout,
                                            const float* __restrict__ bias)
{
    extern __shared__ __half gsm[];
    const int tid = threadIdx.x;
    const int wid = tid >> 5, lane = tid & 31;
    const int wm = (wid >> 1) * 64, wn = (wid & 1) * 64;
    const uint32_t sbase = smem_u32(gsm);

    auto prefetch = [&](int s, int k0) {
#pragma unroll
        for (int t = 0; t < 12; t++) {
            int c = tid + t * 256;          // 0..3071
            const __half* g;
            uint32_t abase;
            int row, seg;
            if (t < 8) {                    // A
                row = c >> 3; seg = c & 7;
                g = A + (size_t)(m0 + row) * DMODEL + k0 + seg * 8;
                abase = 0;
            } else {                        // B
                int rc = c - 2048;
                row = rc >> 3; seg = rc & 7;
                g = B + (size_t)(n0 + row) * DMODEL + k0 + seg * 8;
                abase = G2A_ELE;
            }
            cp16(sbase + (uint32_t)(s * G2STAGE_ELE + abase) * 2 + gswz(row, seg) * 2, g);
        }
    };
    prefetch(0, 0);  cp_commit();
    prefetch(1, 64); cp_commit();

    float acc[4][8][4];
#pragma unroll
    for (int i = 0; i < 4; i++)
#pragma unroll
        for (int j = 0; j < 8; j++)
#pragma unroll
            for (int e = 0; e < 4; e++) acc[i][j][e] = 0.f;

    uint32_t af[2][4][4], b4[2][4][4];

    const int NC = DMODEL / 64;   // 16 slab iterations
    for (int c = 0; c < NC; c++) {
        cp_wait<1>();
        __syncthreads();

        if (c + 2 < NC) prefetch((c + 2) % 3, (c + 2) * 64);
        cp_commit();

        const int s = c % 3;
        const uint32_t st = sbase + (uint32_t)(s * G2STAGE_ELE) * 2;

        auto ldfrag = [&](int buf, int ks) {
#pragma unroll
            for (int mf = 0; mf < 4; mf++)
                ldsm4(af[buf][mf], st + gswz(wm + mf * 16 + (lane & 15),
                                             2 * ks + (lane >> 4)) * 2);
#pragma unroll
            for (int p = 0; p < 4; p++)
                ldsm4(b4[buf][p], st + (uint32_t)(G2A_ELE * 2)
                          + gswz(wn + p * 16 + (lane & 15), 2 * ks + (lane >> 4)) * 2);
        };

        ldfrag(0, 0);
#pragma unroll
        for (int ks = 0; ks < 4; ks++) {
            const int cur = ks & 1, nxt = cur ^ 1;
            if (ks < 3) ldfrag(nxt, ks + 1);
#pragma unroll
            for (int p = 0; p < 4; p++)
#pragma unroll
                for (int mf = 0; mf < 4; mf++) {
                    mma16816(acc[mf][2 * p],     af[cur][mf], b4[cur][p][0], b4[cur][p][2]);
                    mma16816(acc[mf][2 * p + 1], af[cur][mf], b4[cur][p][1], b4[cur][p][3]);
                }
        }
    }

    const int r0 = lane >> 2, cc = (lane & 3) * 2;
#pragma unroll
    for (int mf = 0; mf < 4; mf++) {
        int m = m0 + wm + mf * 16 + r0;
#pragma unroll
        for (int nf = 0; nf < 8; nf++) {
            int n = n0 + wn + (nf >> 1) * 16 + (nf & 1) * 8 + cc;
            float* a = acc[mf][nf];
            if (MODE == 0) {
                *(uint32_t*)(hout + (size_t)m * DMODEL + n) = pack_h2(a[0], a[1]);
                *(uint32_t*)(hout + (size_t)(m + 8) * DMODEL + n) = pack_h2(a[2], a[3]);
            } else {
                float b0 = bias[n], b1 = bias[n + 1];
                *(float2*)(fout + (size_t)m * DMODEL + n) = make_float2(a[0] + b0, a[1] + b1);
                *(float2*)(fout + (size_t)(m + 8) * DMODEL + n) = make_float2(a[2] + b0, a[3] + b1);
            }
        }
    }
}

__global__ __launch_bounds__(256, 1)
void qkv_gemm_kernel()
{
    const int z = blockIdx.z;
    __half* out = (z == 0) ? g_qh : (z == 1) ? g_kh : g_vh;
    gemm_device<0>(g_xh, g_wh + (size_t)z * DMODEL * DMODEL,
                   blockIdx.y * 256, blockIdx.x * 128, out, nullptr, nullptr);
}

__global__ __launch_bounds__(256, 1)
void out_gemm_kernel(const float* __restrict__ bo, float* __restrict__ out)
{
    gemm_device<1>(g_ch, g_wh + (size_t)3 * DMODEL * DMODEL,
                   blockIdx.y * 256, blockIdx.x * 128, nullptr, out, bo);
}

// ---------------------------------------------------------------------------
// Flash attention: fp16 HMMA, causal, no-max softmax, MUFU ex2.approx.
// CTA = 128 q-rows with 4 WARPS x m32 (two m16 frags each): K/V fragments
// are shared across both m-frags, halving per-CTA ldsm traffic vs 8xm16.
// KV tiles of 64, 3-stage cp.async, one sync per tile, stride-72 smem,
// half-tile processing, masked/unmasked paths.
// ---------------------------------------------------------------------------
#define FSTRIDE 72
#define FQ_ELE (128*FSTRIDE)        // 9216 halves
#define FKV_ELE (64*FSTRIDE)        // 4608 halves
#define FSTAGE_ELE (2*FKV_ELE)      // K + V
#define FLASH_SMEM_BYTES ((FQ_ELE + 3*FSTAGE_ELE)*2)   // 73728

template<bool MASKED>
__device__ __forceinline__ void flash_half(
    int c32, int lr32, int rowlo, const int* r0g, int cq, int lane,
    uint32_t kbase, uint32_t vbase,
    const uint32_t (&qa)[2][4][4],
    float (&oacc)[2][8][4], float (&l)[2][2])
{
    uint32_t pa[2][2][4];           // [mf][jp2]
    bool act2[2];

    // S = Q K^T for 2 jp sub-tiles (16 kv cols each), exp -> P
#pragma unroll
    for (int jp2 = 0; jp2 < 2; jp2++) {
        const int c16 = c32 + 16 * jp2;
        act2[jp2] = !MASKED || (c16 <= rowlo + 31);
        if (MASKED && !act2[jp2]) continue;
        float sc[2][2][4] = {};     // [mf][jj]
        uint32_t kb[4];
        const int jrow = lr32 + 16 * jp2 + (lane & 15);
#pragma unroll
        for (int ks = 0; ks < 4; ks++) {
            ldsm4(kb, kbase + (uint32_t)(jrow * FSTRIDE + ks * 16 + (lane >> 4) * 8) * 2);
#pragma unroll
            for (int mf = 0; mf < 2; mf++) {
                mma16816(sc[mf][0], qa[mf][ks], kb[0], kb[2]);
                mma16816(sc[mf][1], qa[mf][ks], kb[1], kb[3]);
            }
        }
#pragma unroll
        for (int mf = 0; mf < 2; mf++)
#pragma unroll
            for (int jj = 0; jj < 2; jj++) {
                float p0, p1, p2, p3;
                if (MASKED) {
                    const int cg = c16 + 8 * jj + cq;
                    p0 = (cg     <= r0g[mf]    ) ? fexp2(sc[mf][jj][0] * K1F) : 0.f;
                    p1 = (cg + 1 <= r0g[mf]    ) ? fexp2(sc[mf][jj][1] * K1F) : 0.f;
                    p2 = (cg     <= r0g[mf] + 8) ? fexp2(sc[mf][jj][2] * K1F) : 0.f;
                    p3 = (cg + 1 <= r0g[mf] + 8) ? fexp2(sc[mf][jj][3] * K1F) : 0.f;
                } else {
                    p0 = fexp2(sc[mf][jj][0] * K1F);
                    p1 = fexp2(sc[mf][jj][1] * K1F);
                    p2 = fexp2(sc[mf][jj][2] * K1F);
                    p3 = fexp2(sc[mf][jj][3] * K1F);
                }
                l[mf][0] += p0 + p1;
                l[mf][1] += p2 + p3;
                pa[mf][jp2][2 * jj]     = pack_h2(p0, p1);
                pa[mf][jp2][2 * jj + 1] = pack_h2(p2, p3);
            }
    }

    // O += P V (partial over this half's 32 kv rows); vb shared across mf
#pragma unroll
    for (int jpd = 0; jpd < 4; jpd++) {
        uint32_t vb[4];
#pragma unroll
        for (int jp2 = 0; jp2 < 2; jp2++) {
            if (MASKED && !act2[jp2]) continue;
            const int vrow = lr32 + 16 * jp2 + (lane & 15);
            ldsm4t(vb, vbase + (uint32_t)(vrow * FSTRIDE + 16 * jpd + (lane >> 4) * 8) * 2);
#pragma unroll
            for (int mf = 0; mf < 2; mf++) {
                mma16816(oacc[mf][2 * jpd],     pa[mf][jp2], vb[0], vb[1]);
                mma16816(oacc[mf][2 * jpd + 1], pa[mf][jp2], vb[2], vb[3]);
            }
        }
    }
}

__global__ __launch_bounds__(128, 3)
void flash_kernel()
{
    extern __shared__ __half fsm[];
    const int tid = threadIdx.x, wid = tid >> 5, lane = tid & 31;
    const int qi = (int)gridDim.x - 1 - (int)blockIdx.x;   // big tiles first
    const int h = blockIdx.y, b = blockIdx.z;
    const int q0 = qi * 128;
    const int n_tiles = 2 * qi + 2;
    const uint32_t sbase = smem_u32(fsm);
    const size_t gb = (size_t)b * SEQ * DMODEL + (size_t)h * DHEAD;

    // Q tile: 128 x 64 halves (1024 chunks / 128 threads)
#pragma unroll
    for (int t = 0; t < 8; t++) {
        int c = tid + t * 128;
        int row = c >> 3, seg = c & 7;
        cp16(sbase + (uint32_t)(row * FSTRIDE + seg * 8) * 2,
             g_qh + gb + (size_t)(q0 + row) * DMODEL + seg * 8);
    }
    cp_commit();

    auto pre_kv = [&](int t, int s) {
        int kv0 = t * 64;
#pragma unroll
        for (int u = 0; u < 8; u++) {
            int c = tid + u * 128;          // 0..1023
            int arr = c >> 9;               // 0=K, 1=V
            int rc = c & 511;
            int row = rc >> 3, seg = rc & 7;
            const __half* g = (arr ? g_vh : g_kh) + gb + (size_t)(kv0 + row) * DMODEL + seg * 8;
            cp16(sbase + (uint32_t)(FQ_ELE + s * FSTAGE_ELE + arr * FKV_ELE
                                    + row * FSTRIDE + seg * 8) * 2, g);
        }
    };
    pre_kv(0, 0); cp_commit();
    pre_kv(1, 1); cp_commit();

    cp_wait<1>();
    __syncthreads();

    // Resident Q A-fragments: 2 m16 frags x 4 k-steps
    uint32_t qa[2][4][4];
#pragma unroll
    for (int mf = 0; mf < 2; mf++)
#pragma unroll
        for (int ks = 0; ks < 4; ks++)
            ldsm4(qa[mf][ks], sbase + (uint32_t)((wid * 32 + mf * 16 + (lane & 15)) * FSTRIDE
                                                 + ks * 16 + (lane >> 4) * 8) * 2);

    float oacc[2][8][4];
#pragma unroll
    for (int mf = 0; mf < 2; mf++)
#pragma unroll
        for (int j = 0; j < 8; j++)
#pragma unroll
            for (int e = 0; e < 4; e++) oacc[mf][j][e] = 0.f;
    float l[2][2] = {};

    const int rowlo = q0 + wid * 32;           // warp's lowest q row
    int r0g[2];
    r0g[0] = rowlo + (lane >> 2);
    r0g[1] = rowlo + 16 + (lane >> 2);
    const int cq = (lane & 3) * 2;

    for (int t = 0; t < n_tiles; t++) {
        if (t > 0) {
            cp_wait<1>();
            __syncthreads();
        }
        if (t + 2 < n_tiles) pre_kv(t + 2, (t + 2) % 3);
        cp_commit();

        const int s = t % 3, kv0 = t * 64;
        const uint32_t kbase = sbase + (uint32_t)(FQ_ELE + s * FSTAGE_ELE) * 2;
        const uint32_t vbase = kbase + (uint32_t)FKV_ELE * 2;

        if (kv0 + 63 <= rowlo) {
            flash_half<false>(kv0,      0,  rowlo, r0g, cq, lane, kbase, vbase, qa, oacc, l);
            flash_half<false>(kv0 + 32, 32, rowlo, r0g, cq, lane, kbase, vbase, qa, oacc, l);
        } else if (kv0 <= rowlo + 31) {
            flash_half<true>(kv0, 0, rowlo, r0g, cq, lane, kbase, vbase, qa, oacc, l);
            if (kv0 + 32 <= rowlo + 31)
                flash_half<true>(kv0 + 32, 32, rowlo, r0g, cq, lane, kbase, vbase, qa, oacc, l);
        }
    }

    // Row sums across the quad, normalize, store ctx fp16
#pragma unroll
    for (int mf = 0; mf < 2; mf++) {
        l[mf][0] += __shfl_xor_sync(0xffffffffu, l[mf][0], 1);
        l[mf][0] += __shfl_xor_sync(0xffffffffu, l[mf][0], 2);
        l[mf][1] += __shfl_xor_sync(0xffffffffu, l[mf][1], 1);
        l[mf][1] += __shfl_xor_sync(0xffffffffu, l[mf][1], 2);
        const float inv0 = 1.0f / l[mf][0], inv1 = 1.0f / l[mf][1];
        const size_t rA = gb + (size_t)r0g[mf] * DMODEL;
        const size_t rB = gb + (size_t)(r0g[mf] + 8) * DMODEL;
#pragma unroll
        for (int j = 0; j < 8; j++) {
            *(uint32_t*)(g_ch + rA + 8 * j + cq) =
                pack_h2(oacc[mf][j][0] * inv0, oacc[mf][j][1] * inv0);
            *(uint32_t*)(g_ch + rB + 8 * j + cq) =
                pack_h2(oacc[mf][j][2] * inv1, oacc[mf][j][3] * inv1);
        }
    }
}

// ---------------------------------------------------------------------------
extern "C" void kernel_launch(void* const* d_in, const int* in_sizes, int n_in,
                              void* d_out, int out_size)
{
    const float* x  = (const float*)d_in[0];
    const float* Wq = (const float*)d_in[1];
    const float* Wk = (const float*)d_in[2];
    const float* Wv = (const float*)d_in[3];
    const float* Wo = (const float*)d_in[4];
    const float* bo = (const float*)d_in[5];
    float* out = (float*)d_out;

    cudaFuncSetAttribute(qkv_gemm_kernel, cudaFuncAttributeMaxDynamicSharedMemorySize, GEMM_SMEM_BYTES);
    cudaFuncSetAttribute(out_gemm_kernel, cudaFuncAttributeMaxDynamicSharedMemorySize, GEMM_SMEM_BYTES);
    cudaFuncSetAttribute(flash_kernel,    cudaFuncAttributeMaxDynamicSharedMemorySize, FLASH_SMEM_BYTES);

    // 1. x -> fp16
    xconv_kernel<<<MROWS * DMODEL / 1024, 256>>>(x);

    // 2. transpose + convert weights to fp16
    wconv_kernel<<<dim3(DMODEL / 32, DMODEL / 32, 4), dim3(32, 8)>>>(Wq, Wk, Wv, Wo);

    // 3. QKV projections (fp16 HMMA, 256x128 tiles)
    qkv_gemm_kernel<<<dim3(DMODEL / 128, MROWS / 256, 3), 256, GEMM_SMEM_BYTES>>>();

    // 4. Flash attention (fp16 HMMA, 4 warps x m32, MUFU exp)
    flash_kernel<<<dim3(SEQ / 128, NHEAD, BBATCH), 128, FLASH_SMEM_BYTES>>>();

    // 5. Output projection + bias (fp32 out)
    out_gemm_kernel<<<dim3(DMODEL / 128, MROWS / 256, 1), 256, GEMM_SMEM_BYTES>>>(bo, out);
}